// round 13
// baseline (speedup 1.0000x reference)
#include <cuda_runtime.h>
#include <math.h>
#include <stdint.h>

#define SEQ    2048
#define DMODEL 1024
#define NH     16
#define NKVH   4
#define HDIM   64
#define LATD   256
#define WINSZ  256

// ---------------------------------------------------------------------------
// Scratch (device globals; no allocation allowed). Activations in bf16.
// ---------------------------------------------------------------------------
__device__ uint16_t g_x1  [SEQ * DMODEL];
__device__ uint16_t g_q   [SEQ * DMODEL];
__device__ uint16_t g_lat [SEQ * LATD];
__device__ uint16_t g_k   [SEQ * LATD];
__device__ uint16_t g_v   [SEQ * LATD];
__device__ uint16_t g_attn[SEQ * DMODEL];

// bf16 weights, TRANSPOSED to [N][K], concatenated (element offsets)
#define GWQ  0
#define GKV  1048576
#define GKUP 1310720
#define GVUP 1376256
#define GWO  1441792
#define LWQ  2490368
#define LWK  3538944
#define LWV  3801088
#define LWO  4063232
__device__ uint16_t g_w[5111808];

// ---------------------------------------------------------------------------
// Helpers
// ---------------------------------------------------------------------------
__device__ __forceinline__ uint16_t f2bf(float x) {
    uint16_t r;
    asm("cvt.rn.bf16.f32 %0, %1;" : "=h"(r) : "f"(x));
    return r;
}
__device__ __forceinline__ uint32_t pack_bf16(float lo, float hi) {
    uint32_t d;
    asm("cvt.rn.bf16x2.f32 %0, %1, %2;" : "=r"(d) : "f"(hi), "f"(lo));
    return d;
}
__device__ __forceinline__ float bf_lo(uint32_t w) { return __uint_as_float(w << 16); }
__device__ __forceinline__ float bf_hi(uint32_t w) { return __uint_as_float(w & 0xffff0000u); }

__device__ __forceinline__ void mma_bf16(float* c,
                                         uint32_t a0, uint32_t a1,
                                         uint32_t a2, uint32_t a3,
                                         uint32_t b0, uint32_t b1) {
    asm volatile(
        "mma.sync.aligned.m16n8k16.row.col.f32.bf16.bf16.f32 "
        "{%0,%1,%2,%3}, {%4,%5,%6,%7}, {%8,%9}, {%0,%1,%2,%3};\n"
        : "+f"(c[0]), "+f"(c[1]), "+f"(c[2]), "+f"(c[3])
        : "r"(a0), "r"(a1), "r"(a2), "r"(a3), "r"(b0), "r"(b1));
}

__device__ __forceinline__ void cp16(uint32_t s, const void* g) {
    asm volatile("cp.async.cg.shared.global [%0], [%1], 16;\n" :: "r"(s), "l"(g));
}
__device__ __forceinline__ void cp_commit() {
    asm volatile("cp.async.commit_group;\n");
}
template<int N>
__device__ __forceinline__ void cp_wait() {
    asm volatile("cp.async.wait_group %0;\n" :: "n"(N));
}
__device__ __forceinline__ uint32_t s2u(const void* p) {
    return (uint32_t)__cvta_generic_to_shared(p);
}
__device__ __forceinline__ void ldsm_x4(uint32_t& r0, uint32_t& r1,
                                        uint32_t& r2, uint32_t& r3, uint32_t a) {
    asm volatile("ldmatrix.sync.aligned.m8n8.x4.shared.b16 {%0,%1,%2,%3}, [%4];"
                 : "=r"(r0), "=r"(r1), "=r"(r2), "=r"(r3) : "r"(a));
}
__device__ __forceinline__ void ldsm_x4_t(uint32_t& r0, uint32_t& r1,
                                          uint32_t& r2, uint32_t& r3, uint32_t a) {
    asm volatile("ldmatrix.sync.aligned.m8n8.x4.trans.shared.b16 {%0,%1,%2,%3}, [%4];"
                 : "=r"(r0), "=r"(r1), "=r"(r2), "=r"(r3) : "r"(a));
}

// ---------------------------------------------------------------------------
// Fused weight transpose+bf16: one launch, 4992 tile-blocks over 9 segments.
// dst[n][k] = bf16(src[k][n])
// ---------------------------------------------------------------------------
__global__ void transpose_all(uint16_t* __restrict__ gw,
    const float* s0, const float* s1, const float* s2, const float* s3,
    const float* s4, const float* s5, const float* s6, const float* s7,
    const float* s8) {
    __shared__ float t[32][33];
    int tb = blockIdx.x;
    const float* src; uint16_t* dst; int K, N, tn;
    if (tb < 1024)      { src = s0; dst = gw + GWQ;  K = 1024; N = 1024; tn = tb; }
    else if (tb < 1280) { src = s1; dst = gw + GKV;  K = 1024; N = 256;  tn = tb - 1024; }
    else if (tb < 1344) { src = s2; dst = gw + GKUP; K = 256;  N = 256;  tn = tb - 1280; }
    else if (tb < 1408) { src = s3; dst = gw + GVUP; K = 256;  N = 256;  tn = tb - 1344; }
    else if (tb < 2432) { src = s4; dst = gw + GWO;  K = 1024; N = 1024; tn = tb - 1408; }
    else if (tb < 3456) { src = s5; dst = gw + LWQ;  K = 1024; N = 1024; tn = tb - 2432; }
    else if (tb < 3712) { src = s6; dst = gw + LWK;  K = 1024; N = 256;  tn = tb - 3456; }
    else if (tb < 3968) { src = s7; dst = gw + LWV;  K = 1024; N = 256;  tn = tb - 3712; }
    else                { src = s8; dst = gw + LWO;  K = 1024; N = 1024; tn = tb - 3968; }
    int tilesN = N >> 5;
    int n0 = (tn % tilesN) * 32, k0 = (tn / tilesN) * 32;
    int x = threadIdx.x, y = threadIdx.y;
    #pragma unroll
    for (int i = 0; i < 32; i += 8)
        t[y + i][x] = src[(size_t)(k0 + y + i) * N + n0 + x];
    __syncthreads();
    #pragma unroll
    for (int i = 0; i < 32; i += 8)
        dst[(size_t)(n0 + y + i) * K + k0 + x] = f2bf(t[x][y + i]);
}

// ---------------------------------------------------------------------------
// RMSNorm: fp32 in -> bf16 out
// ---------------------------------------------------------------------------
__global__ void rmsnorm_kernel(const float* __restrict__ x,
                               const float* __restrict__ w,
                               uint16_t* __restrict__ y) {
    int row = blockIdx.x;
    int tid = threadIdx.x;
    const float4* xr = (const float4*)(x + (size_t)row * DMODEL);
    float4 v = xr[tid];
    float ss = v.x * v.x + v.y * v.y + v.z * v.z + v.w * v.w;
    __shared__ float red[256];
    red[tid] = ss;
    __syncthreads();
    #pragma unroll
    for (int o = 128; o > 0; o >>= 1) {
        if (tid < o) red[tid] += red[tid + o];
        __syncthreads();
    }
    float r = rsqrtf(red[0] / (float)DMODEL + 1e-6f);
    float4 wv = ((const float4*)w)[tid];
    uint32_t* yw = (uint32_t*)(y + (size_t)row * DMODEL);
    yw[2 * tid]     = pack_bf16(v.x * r * wv.x, v.y * r * wv.y);
    yw[2 * tid + 1] = pack_bf16(v.z * r * wv.z, v.w * r * wv.w);
}

// ---------------------------------------------------------------------------
// Segmented BF16 GEMM: cp.async 2-stage + ldmatrix fragments.
// A bf16 [M][K]; B bf16 [nseg][K] (pre-transposed); warp layout 2m x 4n.
// ---------------------------------------------------------------------------
template<int BM, int BN, int BK>
__global__ __launch_bounds__(256, 2)
void bgemm(const uint16_t* __restrict__ A,
           const uint16_t* __restrict__ B0, void* C0, int n0,
           const uint16_t* __restrict__ B1, void* C1, int n1,
           const uint16_t* __restrict__ B2, void* C2, int n2,
           const float* __restrict__ R, int K, int bfout) {
    constexpr int PW  = BK / 2 + 4;       // word pitch
    constexpr int CPR = BK / 8;           // 16B chunks per row
    constexpr int WM  = BM / 2;
    constexpr int WN  = BN / 4;
    constexpr int MT  = WM / 16;
    constexpr int NT  = WN / 8;
    constexpr int ACP = BM * CPR / 256;   // cp16 per thread per stage
    constexpr int BCP = BN * CPR / 256;

    extern __shared__ uint32_t smw[];
    uint32_t (*As)[BM][PW] = (uint32_t(*)[BM][PW])smw;
    uint32_t (*Bs)[BN][PW] = (uint32_t(*)[BN][PW])(smw + 2 * BM * PW);

    int tid  = threadIdx.x;
    int wid  = tid >> 5;
    int lane = tid & 31;
    int g    = lane >> 2;
    int cq   = lane & 3;
    int l15  = lane & 15;
    int h4   = (lane >> 4) * 4;
    int wm   = (wid & 1) * WM;
    int wn   = (wid >> 1) * WN;
    int r0   = blockIdx.y * BM;
    int c0   = blockIdx.x * BN;

    const uint16_t* Bseg;
    void* Cseg;
    int nseg, segc, segi;
    if (c0 < n0)           { Bseg = B0; Cseg = C0; nseg = n0; segc = c0; segi = 0; }
    else if (c0 < n0 + n1) { Bseg = B1; Cseg = C1; nseg = n1; segc = c0 - n0; segi = 1; }
    else                   { Bseg = B2; Cseg = C2; nseg = n2; segc = c0 - n0 - n1; segi = 2; }
    bool bfo = (bfout >> segi) & 1;

    float acc[MT][NT][4];
    #pragma unroll
    for (int t = 0; t < MT; t++)
        #pragma unroll
        for (int u = 0; u < NT; u++)
            #pragma unroll
            for (int i = 0; i < 4; i++) acc[t][u][i] = 0.0f;

    uint32_t aBase = s2u(&As[0][0][0]);
    uint32_t bBase = s2u(&Bs[0][0][0]);

    // stage 0
    #pragma unroll
    for (int t = 0; t < ACP; t++) {
        int idx = tid + t * 256;
        int ar = idx / CPR, ch = idx % CPR;
        cp16(s2u(&As[0][ar][ch * 4]), A + (size_t)(r0 + ar) * K + ch * 8);
    }
    #pragma unroll
    for (int t = 0; t < BCP; t++) {
        int idx = tid + t * 256;
        int br = idx / CPR, ch = idx % CPR;
        cp16(s2u(&Bs[0][br][ch * 4]), Bseg + (size_t)(segc + br) * K + ch * 8);
    }
    cp_commit();

    int NKB = K / BK;
    for (int kb = 0; kb < NKB; kb++) {
        int b = kb & 1;
        if (kb + 1 < NKB) {
            int k0 = (kb + 1) * BK;
            #pragma unroll
            for (int t = 0; t < ACP; t++) {
                int idx = tid + t * 256;
                int ar = idx / CPR, ch = idx % CPR;
                cp16(s2u(&As[b ^ 1][ar][ch * 4]),
                     A + (size_t)(r0 + ar) * K + k0 + ch * 8);
            }
            #pragma unroll
            for (int t = 0; t < BCP; t++) {
                int idx = tid + t * 256;
                int br = idx / CPR, ch = idx % CPR;
                cp16(s2u(&Bs[b ^ 1][br][ch * 4]),
                     Bseg + (size_t)(segc + br) * K + k0 + ch * 8);
            }
            cp_commit();
            cp_wait<1>();
        } else {
            cp_wait<0>();
        }
        __syncthreads();

        uint32_t aB = aBase + (uint32_t)(b * BM * PW * 4);
        uint32_t bB = bBase + (uint32_t)(b * BN * PW * 4);

        #pragma unroll
        for (int k16 = 0; k16 < BK / 16; k16++) {
            int kw = k16 * 8 + h4;
            uint32_t af[MT][4];
            #pragma unroll
            for (int t = 0; t < MT; t++)
                ldsm_x4(af[t][0], af[t][1], af[t][2], af[t][3],
                        aB + (uint32_t)(((wm + 16 * t + l15) * PW + kw) * 4));
            uint32_t bf[NT][2];
            #pragma unroll
            for (int u2 = 0; u2 < NT / 2; u2++)
                ldsm_x4(bf[2 * u2][0], bf[2 * u2 + 1][0],
                        bf[2 * u2][1], bf[2 * u2 + 1][1],
                        bB + (uint32_t)(((wn + 16 * u2 + l15) * PW + kw) * 4));
            #pragma unroll
            for (int t = 0; t < MT; t++)
                #pragma unroll
                for (int u = 0; u < NT; u++)
                    mma_bf16(acc[t][u], af[t][0], af[t][1], af[t][2], af[t][3],
                             bf[u][0], bf[u][1]);
        }
        __syncthreads();
    }

    #pragma unroll
    for (int t = 0; t < MT; t++) {
        int row = r0 + wm + 16 * t + g;
        #pragma unroll
        for (int u = 0; u < NT; u++) {
            int col = segc + wn + 8 * u + 2 * cq;
            size_t off0 = (size_t)row * nseg + col;
            size_t off1 = (size_t)(row + 8) * nseg + col;
            if (bfo) {
                uint16_t* Cb = (uint16_t*)Cseg;
                *(uint32_t*)(Cb + off0) = pack_bf16(acc[t][u][0], acc[t][u][1]);
                *(uint32_t*)(Cb + off1) = pack_bf16(acc[t][u][2], acc[t][u][3]);
            } else {
                float* Cf = (float*)Cseg;
                float2 r0v = make_float2(0.f, 0.f), r1v = make_float2(0.f, 0.f);
                if (R) {
                    r0v = *(const float2*)(R + off0);
                    r1v = *(const float2*)(R + off1);
                }
                *(float2*)(Cf + off0) = make_float2(acc[t][u][0] + r0v.x,
                                                    acc[t][u][1] + r0v.y);
                *(float2*)(Cf + off1) = make_float2(acc[t][u][2] + r1v.x,
                                                    acc[t][u][3] + r1v.y);
            }
        }
    }
}

// ---------------------------------------------------------------------------
// Fast RoPE + qk_norm on bf16 q/k: one block per s, 20 warps = 20 heads.
// Q scaled by 1/8 (exact pow2; folded softmax scale).
// ---------------------------------------------------------------------------
__global__ __launch_bounds__(640)
void rope_qknorm_fast(uint16_t* __restrict__ q, uint16_t* __restrict__ k,
                      float base) {
    __shared__ float scs[32], ssn[32];
    int s   = blockIdx.x;
    int tid = threadIdx.x;
    int w   = tid >> 5;
    int i   = tid & 31;

    if (tid < 32) {
        float invf = powf(base, -((float)(2 * tid) / (float)HDIM));
        float ang = (float)s * invf;
        sincosf(ang, &ssn[tid], &scs[tid]);
    }
    __syncthreads();

    uint32_t* p;
    float scale;
    if (w < NH) { p = (uint32_t*)(q + (size_t)s * DMODEL + w * HDIM); scale = 0.125f; }
    else        { p = (uint32_t*)(k + (size_t)s * LATD + (w - NH) * HDIM); scale = 1.0f; }

    uint32_t xw = p[i];
    float xe = bf_lo(xw), xo = bf_hi(xw);
    float cs = scs[i], sn = ssn[i];
    float re = xe * cs - xo * sn;
    float ro = xe * sn + xo * cs;

    float ss = re * re + ro * ro;
    #pragma unroll
    for (int o = 16; o > 0; o >>= 1)
        ss += __shfl_xor_sync(0xffffffffu, ss, o);

    float r = rsqrtf(ss / (float)HDIM + 1e-6f) * scale;
    p[i] = pack_bf16(re * r, ro * r);
}

// ---------------------------------------------------------------------------
// BF16 mma flash attention. Block = (128-q tile, head), 256 threads / 8 warps
// (warp w owns q-rows [w*16, w*16+16)). K/V tiles of 64 keys, cp.async
// double-buffered; ldmatrix K (non-trans) + V (trans); P stays in registers.
// SMEM words (pitch 36): Qs[128] Ks[2][64] Vs[2][64] = 55296 B
// ---------------------------------------------------------------------------
#define APW 36
__global__ __launch_bounds__(256, 2)
void fattn_mma(const uint16_t* __restrict__ Q, const uint16_t* __restrict__ K,
               const uint16_t* __restrict__ V, uint16_t* __restrict__ O,
               int win) {
    extern __shared__ uint32_t smw[];
    uint32_t (*Qs)[APW]     = (uint32_t(*)[APW])smw;
    uint32_t (*Ks)[64][APW] = (uint32_t(*)[64][APW])(smw + 128 * APW);
    uint32_t (*Vs)[64][APW] = (uint32_t(*)[64][APW])(smw + 128 * APW + 2 * 64 * APW);

    int qt  = gridDim.x - 1 - blockIdx.x;   // heavy tiles first
    int h   = blockIdx.y;
    int kvh = h >> 2;
    int tid = threadIdx.x;
    int wid = tid >> 5;
    int lane = tid & 31;
    int g   = lane >> 2;
    int cq  = lane & 3;
    int l15 = lane & 15;
    int h4  = (lane >> 4) * 4;
    int m0  = wid * 16;
    int q0  = qt * 128;

    int jt0 = 0;
    if (win > 0) {
        int lo = q0 - (WINSZ - 1);
        jt0 = (lo > 0) ? (lo >> 6) : 0;
    }
    int jtMax = 2 * qt + 1;

    // stage first K/V tile
    {
        int j0 = jt0 * 64;
        #pragma unroll
        for (int t = 0; t < 2; t++) {
            int idx = tid + t * 256;
            int jj = idx >> 3, ch = idx & 7;
            cp16(s2u(&Ks[0][jj][ch * 4]),
                 K + (size_t)(j0 + jj) * LATD + kvh * HDIM + ch * 8);
            cp16(s2u(&Vs[0][jj][ch * 4]),
                 V + (size_t)(j0 + jj) * LATD + kvh * HDIM + ch * 8);
        }
        cp_commit();
    }

    // stage Q tile (128 rows, bf16, pre-scaled by 1/8)
    #pragma unroll
    for (int t = 0; t < 4; t++) {
        int idx = tid + t * 256;
        int qi = idx >> 3, ch = idx & 7;
        *(uint4*)&Qs[qi][ch * 4] =
            *(const uint4*)(Q + (size_t)(q0 + qi) * DMODEL + h * HDIM + ch * 8);
    }
    __syncthreads();

    // hoist Q fragments via ldmatrix (4 k16 windows over HDIM)
    uint32_t qBase = s2u(&Qs[0][0]);
    uint32_t qf[4][4];
    #pragma unroll
    for (int k16 = 0; k16 < 4; k16++)
        ldsm_x4(qf[k16][0], qf[k16][1], qf[k16][2], qf[k16][3],
                qBase + (uint32_t)(((m0 + l15) * APW + k16 * 8 + h4) * 4));

    float o[8][4];
    #pragma unroll
    for (int u = 0; u < 8; u++)
        #pragma unroll
        for (int i = 0; i < 4; i++) o[u][i] = 0.0f;
    float mrow0 = -60.0f, mrow1 = -60.0f;
    float lrow0 = 0.0f,   lrow1 = 0.0f;

    int row0 = q0 + m0 + g;
    int row1 = row0 + 8;
    uint32_t kBase = s2u(&Ks[0][0][0]);
    uint32_t vBase = s2u(&Vs[0][0][0]);

    for (int jt = jt0; jt <= jtMax; jt++) {
        int b = (jt - jt0) & 1;
        if (jt < jtMax) {
            int j0 = (jt + 1) * 64;
            #pragma unroll
            for (int t = 0; t < 2; t++) {
                int idx = tid + t * 256;
                int jj = idx >> 3, ch = idx & 7;
                cp16(s2u(&Ks[b ^ 1][jj][ch * 4]),
                     K + (size_t)(j0 + jj) * LATD + kvh * HDIM + ch * 8);
                cp16(s2u(&Vs[b ^ 1][jj][ch * 4]),
                     V + (size_t)(j0 + jj) * LATD + kvh * HDIM + ch * 8);
            }
            cp_commit();
            cp_wait<1>();
        } else {
            cp_wait<0>();
        }
        __syncthreads();

        int j0 = jt * 64;
        uint32_t kB = kBase + (uint32_t)(b * 64 * APW * 4);
        uint32_t vB = vBase + (uint32_t)(b * 64 * APW * 4);

        // S = Q K^T  (keys = n dim; B frags non-trans from [key][hd])
        float s[8][4];
        #pragma unroll
        for (int u = 0; u < 8; u++)
            #pragma unroll
            for (int i = 0; i < 4; i++) s[u][i] = 0.0f;

        #pragma unroll
        for (int k16 = 0; k16 < 4; k16++) {
            int kw = k16 * 8 + h4;
            #pragma unroll
            for (int u2 = 0; u2 < 4; u2++) {
                uint32_t b00, b01, b10, b11;
                ldsm_x4(b00, b10, b01, b11,
                        kB + (uint32_t)(((u2 * 16 + l15) * APW + kw) * 4));
                mma_bf16(s[2 * u2],     qf[k16][0], qf[k16][1], qf[k16][2],
                         qf[k16][3], b00, b01);
                mma_bf16(s[2 * u2 + 1], qf[k16][0], qf[k16][1], qf[k16][2],
                         qf[k16][3], b10, b11);
            }
        }

        // mask
        #pragma unroll
        for (int u = 0; u < 8; u++) {
            int col = j0 + u * 8 + 2 * cq;
            #pragma unroll
            for (int i = 0; i < 4; i++) {
                int q  = (i < 2) ? row0 : row1;
                int kj = col + (i & 1);
                bool vis = (kj <= q) && (win == 0 || (q - kj) < win);
                if (!vis) s[u][i] = -1e30f;
            }
        }

        // online softmax
        float rm0 = -1e30f, rm1 = -1e30f;
        #pragma unroll
        for (int u = 0; u < 8; u++) {
            rm0 = fmaxf(rm0, fmaxf(s[u][0], s[u][1]));
            rm1 = fmaxf(rm1, fmaxf(s[u][2], s[u][3]));
        }
        #pragma unroll
        for (int off = 1; off <= 2; off <<= 1) {
            rm0 = fmaxf(rm0, __shfl_xor_sync(0xffffffffu, rm0, off));
            rm1 = fmaxf(rm1, __shfl_xor_sync(0xffffffffu, rm1, off));
        }
        float mn0 = fmaxf(mrow0, rm0);
        float mn1 = fmaxf(mrow1, rm1);
        float al0 = __expf(mrow0 - mn0);
        float al1 = __expf(mrow1 - mn1);
        float rs0 = 0.0f, rs1 = 0.0f;
        #pragma unroll
        for (int u = 0; u < 8; u++) {
            float p0 = __expf(s[u][0] - mn0);
            float p1 = __expf(s[u][1] - mn0);
            float p2 = __expf(s[u][2] - mn1);
            float p3 = __expf(s[u][3] - mn1);
            s[u][0] = p0; s[u][1] = p1; s[u][2] = p2; s[u][3] = p3;
            rs0 += p0 + p1;
            rs1 += p2 + p3;
        }
        #pragma unroll
        for (int off = 1; off <= 2; off <<= 1) {
            rs0 += __shfl_xor_sync(0xffffffffu, rs0, off);
            rs1 += __shfl_xor_sync(0xffffffffu, rs1, off);
        }
        lrow0 = lrow0 * al0 + rs0;
        lrow1 = lrow1 * al1 + rs1;
        mrow0 = mn0;
        mrow1 = mn1;
        #pragma unroll
        for (int u = 0; u < 8; u++) {
            o[u][0] *= al0; o[u][1] *= al0;
            o[u][2] *= al1; o[u][3] *= al1;
        }

        // P fragments directly from S accumulators (no SMEM round-trip)
        uint32_t pf[4][4];
        #pragma unroll
        for (int w = 0; w < 4; w++) {
            pf[w][0] = pack_bf16(s[2 * w][0],     s[2 * w][1]);
            pf[w][1] = pack_bf16(s[2 * w][2],     s[2 * w][3]);
            pf[w][2] = pack_bf16(s[2 * w + 1][0], s[2 * w + 1][1]);
            pf[w][3] = pack_bf16(s[2 * w + 1][2], s[2 * w + 1][3]);
        }

        // O += P @ V  (V trans-ldmatrix from [key][hd])
        #pragma unroll
        for (int w = 0; w < 4; w++) {
            #pragma unroll
            for (int u2 = 0; u2 < 4; u2++) {
                uint32_t c00, c01, c10, c11;
                ldsm_x4_t(c00, c01, c10, c11,
                          vB + (uint32_t)(((w * 16 + l15) * APW + u2 * 8 + h4) * 4));
                mma_bf16(o[2 * u2],     pf[w][0], pf[w][1], pf[w][2], pf[w][3],
                         c00, c01);
                mma_bf16(o[2 * u2 + 1], pf[w][0], pf[w][1], pf[w][2], pf[w][3],
                         c10, c11);
            }
        }
        __syncthreads();
    }

    float inv0 = 1.0f / lrow0;
    float inv1 = 1.0f / lrow1;
    #pragma unroll
    for (int u = 0; u < 8; u++) {
        int col = u * 8 + 2 * cq;
        *(uint32_t*)(O + (size_t)row0 * DMODEL + h * HDIM + col) =
            pack_bf16(o[u][0] * inv0, o[u][1] * inv0);
        *(uint32_t*)(O + (size_t)row1 * DMODEL + h * HDIM + col) =
            pack_bf16(o[u][2] * inv1, o[u][3] * inv1);
    }
}

// ---------------------------------------------------------------------------
// Launch
// ---------------------------------------------------------------------------
extern "C" void kernel_launch(void* const* d_in, const int* in_sizes, int n_in,
                              void* d_out, int out_size) {
    (void)in_sizes; (void)n_in; (void)out_size;

    const float* hidden   = (const float*)d_in[0];
    const float* norm1_w  = (const float*)d_in[1];
    const float* norm2_w  = (const float*)d_in[2];
    const float* w_g_wq   = (const float*)d_in[3];
    const float* w_g_kvdn = (const float*)d_in[4];
    const float* w_g_k_up = (const float*)d_in[5];
    const float* w_g_v_up = (const float*)d_in[6];
    const float* w_g_wo   = (const float*)d_in[7];
    const float* w_l_wq   = (const float*)d_in[8];
    const float* w_l_wk   = (const float*)d_in[9];
    const float* w_l_wv   = (const float*)d_in[10];
    const float* w_l_wo   = (const float*)d_in[11];
    float* out = (float*)d_out;

    uint16_t *x1, *q, *lat, *k, *v, *attn, *gw;
    cudaGetSymbolAddress((void**)&x1,   g_x1);
    cudaGetSymbolAddress((void**)&q,    g_q);
    cudaGetSymbolAddress((void**)&lat,  g_lat);
    cudaGetSymbolAddress((void**)&k,    g_k);
    cudaGetSymbolAddress((void**)&v,    g_v);
    cudaGetSymbolAddress((void**)&attn, g_attn);
    cudaGetSymbolAddress((void**)&gw,   g_w);

    const int GEMM128_SMEM = 2 * (128 * 20 + 128 * 20) * 4;  // 40960  (BK=32)
    const int GEMM64_SMEM  = 2 * (64 * 36 + 64 * 36) * 4;    // 36864  (BK=64)
    const int ATTN_SMEM    = (128 * APW + 4 * 64 * APW) * 4; // 55296

    cudaFuncSetAttribute(bgemm<128, 128, 32>,
                         cudaFuncAttributeMaxDynamicSharedMemorySize, GEMM128_SMEM);
    cudaFuncSetAttribute(bgemm<64, 64, 64>,
                         cudaFuncAttributeMaxDynamicSharedMemorySize, GEMM64_SMEM);
    cudaFuncSetAttribute(fattn_mma,
                         cudaFuncAttributeMaxDynamicSharedMemorySize, ATTN_SMEM);

    dim3 gridAttn(SEQ / 128, NH);   // (16, 16)

    // ---- Pre-pass: single fused weight transpose+convert ----
    transpose_all<<<4992, dim3(32, 8)>>>(gw,
        w_g_wq, w_g_kvdn, w_g_k_up, w_g_v_up, w_g_wo,
        w_l_wq, w_l_wk, w_l_wv, w_l_wo);

    // ---- Layer 1: global latent attention ----
    rmsnorm_kernel<<<SEQ, 256>>>(hidden, norm1_w, x1);
    bgemm<128, 128, 32><<<dim3(10, 16), 256, GEMM128_SMEM>>>(
        x1, gw + GWQ, q, DMODEL, gw + GKV, lat, LATD,
        nullptr, nullptr, 0, nullptr, DMODEL, /*bfout=*/3);
    bgemm<64, 64, 64><<<dim3(8, 32), 256, GEMM64_SMEM>>>(
        lat, gw + GKUP, k, LATD, gw + GVUP, v, LATD,
        nullptr, nullptr, 0, nullptr, LATD, /*bfout=*/3);
    rope_qknorm_fast<<<SEQ, 640>>>(q, k, 1000000.0f);
    fattn_mma<<<gridAttn, 256, ATTN_SMEM>>>(q, k, v, attn, /*win=*/0);
    bgemm<128, 128, 32><<<dim3(8, 16), 256, GEMM128_SMEM>>>(
        attn, gw + GWO, out, DMODEL, nullptr, nullptr, 0,
        nullptr, nullptr, 0, hidden, DMODEL, /*bfout=*/0);

    // ---- Layer 2: local GQA attention ----
    rmsnorm_kernel<<<SEQ, 256>>>(out, norm2_w, x1);
    bgemm<128, 128, 32><<<dim3(12, 16), 256, GEMM128_SMEM>>>(
        x1, gw + LWQ, q, DMODEL, gw + LWK, k, LATD,
        gw + LWV, v, LATD, nullptr, DMODEL, /*bfout=*/7);
    rope_qknorm_fast<<<SEQ, 640>>>(q, k, 10000.0f);
    fattn_mma<<<gridAttn, 256, ATTN_SMEM>>>(q, k, v, attn, /*win=*/WINSZ);
    bgemm<128, 128, 32><<<dim3(8, 16), 256, GEMM128_SMEM>>>(
        attn, gw + LWO, out, DMODEL, nullptr, nullptr, 0,
        nullptr, nullptr, 0, out, DMODEL, /*bfout=*/0);
}

// round 14
// speedup vs baseline: 1.1709x; 1.1709x over previous
#include <cuda_runtime.h>
#include <math.h>
#include <stdint.h>

#define SEQ    2048
#define DMODEL 1024
#define NH     16
#define NKVH   4
#define HDIM   64
#define LATD   256
#define WINSZ  256

// ---------------------------------------------------------------------------
// Scratch (device globals; no allocation allowed). Activations in bf16.
// ---------------------------------------------------------------------------
__device__ uint16_t g_x1  [SEQ * DMODEL];
__device__ uint16_t g_q   [SEQ * DMODEL];
__device__ uint16_t g_lat [SEQ * LATD];
__device__ uint16_t g_k   [SEQ * LATD];
__device__ uint16_t g_v   [SEQ * LATD];
__device__ uint16_t g_attn[SEQ * DMODEL];

// bf16 weights, TRANSPOSED to [N][K], concatenated (element offsets)
#define GWQ  0
#define GKV  1048576
#define GKUP 1310720
#define GVUP 1376256
#define GWO  1441792
#define LWQ  2490368
#define LWK  3538944
#define LWV  3801088
#define LWO  4063232
__device__ uint16_t g_w[5111808];

// ---------------------------------------------------------------------------
// Helpers
// ---------------------------------------------------------------------------
__device__ __forceinline__ uint16_t f2bf(float x) {
    uint16_t r;
    asm("cvt.rn.bf16.f32 %0, %1;" : "=h"(r) : "f"(x));
    return r;
}
__device__ __forceinline__ uint32_t pack_bf16(float lo, float hi) {
    uint32_t d;
    asm("cvt.rn.bf16x2.f32 %0, %1, %2;" : "=r"(d) : "f"(hi), "f"(lo));
    return d;
}
__device__ __forceinline__ float bf_lo(uint32_t w) { return __uint_as_float(w << 16); }
__device__ __forceinline__ float bf_hi(uint32_t w) { return __uint_as_float(w & 0xffff0000u); }

__device__ __forceinline__ void mma_bf16(float* c,
                                         uint32_t a0, uint32_t a1,
                                         uint32_t a2, uint32_t a3,
                                         uint32_t b0, uint32_t b1) {
    asm volatile(
        "mma.sync.aligned.m16n8k16.row.col.f32.bf16.bf16.f32 "
        "{%0,%1,%2,%3}, {%4,%5,%6,%7}, {%8,%9}, {%0,%1,%2,%3};\n"
        : "+f"(c[0]), "+f"(c[1]), "+f"(c[2]), "+f"(c[3])
        : "r"(a0), "r"(a1), "r"(a2), "r"(a3), "r"(b0), "r"(b1));
}

__device__ __forceinline__ void cp16(uint32_t s, const void* g) {
    asm volatile("cp.async.cg.shared.global [%0], [%1], 16;\n" :: "r"(s), "l"(g));
}
__device__ __forceinline__ void cp_commit() {
    asm volatile("cp.async.commit_group;\n");
}
template<int N>
__device__ __forceinline__ void cp_wait() {
    asm volatile("cp.async.wait_group %0;\n" :: "n"(N));
}
__device__ __forceinline__ uint32_t s2u(const void* p) {
    return (uint32_t)__cvta_generic_to_shared(p);
}
__device__ __forceinline__ void ldsm_x4(uint32_t& r0, uint32_t& r1,
                                        uint32_t& r2, uint32_t& r3, uint32_t a) {
    asm volatile("ldmatrix.sync.aligned.m8n8.x4.shared.b16 {%0,%1,%2,%3}, [%4];"
                 : "=r"(r0), "=r"(r1), "=r"(r2), "=r"(r3) : "r"(a));
}
__device__ __forceinline__ void ldsm_x4_t(uint32_t& r0, uint32_t& r1,
                                          uint32_t& r2, uint32_t& r3, uint32_t a) {
    asm volatile("ldmatrix.sync.aligned.m8n8.x4.trans.shared.b16 {%0,%1,%2,%3}, [%4];"
                 : "=r"(r0), "=r"(r1), "=r"(r2), "=r"(r3) : "r"(a));
}

// ---------------------------------------------------------------------------
// Fused weight transpose+bf16: one launch, 4992 tile-blocks over 9 segments.
// dst[n][k] = bf16(src[k][n])
// ---------------------------------------------------------------------------
__global__ void transpose_all(uint16_t* __restrict__ gw,
    const float* s0, const float* s1, const float* s2, const float* s3,
    const float* s4, const float* s5, const float* s6, const float* s7,
    const float* s8) {
    __shared__ float t[32][33];
    int tb = blockIdx.x;
    const float* src; uint16_t* dst; int K, N, tn;
    if (tb < 1024)      { src = s0; dst = gw + GWQ;  K = 1024; N = 1024; tn = tb; }
    else if (tb < 1280) { src = s1; dst = gw + GKV;  K = 1024; N = 256;  tn = tb - 1024; }
    else if (tb < 1344) { src = s2; dst = gw + GKUP; K = 256;  N = 256;  tn = tb - 1280; }
    else if (tb < 1408) { src = s3; dst = gw + GVUP; K = 256;  N = 256;  tn = tb - 1344; }
    else if (tb < 2432) { src = s4; dst = gw + GWO;  K = 1024; N = 1024; tn = tb - 1408; }
    else if (tb < 3456) { src = s5; dst = gw + LWQ;  K = 1024; N = 1024; tn = tb - 2432; }
    else if (tb < 3712) { src = s6; dst = gw + LWK;  K = 1024; N = 256;  tn = tb - 3456; }
    else if (tb < 3968) { src = s7; dst = gw + LWV;  K = 1024; N = 256;  tn = tb - 3712; }
    else                { src = s8; dst = gw + LWO;  K = 1024; N = 1024; tn = tb - 3968; }
    int tilesN = N >> 5;
    int n0 = (tn % tilesN) * 32, k0 = (tn / tilesN) * 32;
    int x = threadIdx.x, y = threadIdx.y;
    #pragma unroll
    for (int i = 0; i < 32; i += 8)
        t[y + i][x] = src[(size_t)(k0 + y + i) * N + n0 + x];
    __syncthreads();
    #pragma unroll
    for (int i = 0; i < 32; i += 8)
        dst[(size_t)(n0 + y + i) * K + k0 + x] = f2bf(t[x][y + i]);
}

// ---------------------------------------------------------------------------
// RMSNorm: fp32 in -> bf16 out
// ---------------------------------------------------------------------------
__global__ void rmsnorm_kernel(const float* __restrict__ x,
                               const float* __restrict__ w,
                               uint16_t* __restrict__ y) {
    int row = blockIdx.x;
    int tid = threadIdx.x;
    const float4* xr = (const float4*)(x + (size_t)row * DMODEL);
    float4 v = xr[tid];
    float ss = v.x * v.x + v.y * v.y + v.z * v.z + v.w * v.w;
    __shared__ float red[256];
    red[tid] = ss;
    __syncthreads();
    #pragma unroll
    for (int o = 128; o > 0; o >>= 1) {
        if (tid < o) red[tid] += red[tid + o];
        __syncthreads();
    }
    float r = rsqrtf(red[0] / (float)DMODEL + 1e-6f);
    float4 wv = ((const float4*)w)[tid];
    uint32_t* yw = (uint32_t*)(y + (size_t)row * DMODEL);
    yw[2 * tid]     = pack_bf16(v.x * r * wv.x, v.y * r * wv.y);
    yw[2 * tid + 1] = pack_bf16(v.z * r * wv.z, v.w * r * wv.w);
}

// ---------------------------------------------------------------------------
// Segmented BF16 GEMM: cp.async double-buffered (single sync per k-block) +
// ldmatrix fragments. A bf16 [M][K]; B bf16 [nseg][K] (pre-transposed);
// warp layout 2m x 4n.
// ---------------------------------------------------------------------------
template<int BM, int BN, int BK>
__global__ __launch_bounds__(256, 2)
void bgemm(const uint16_t* __restrict__ A,
           const uint16_t* __restrict__ B0, void* C0, int n0,
           const uint16_t* __restrict__ B1, void* C1, int n1,
           const uint16_t* __restrict__ B2, void* C2, int n2,
           const float* __restrict__ R, int K, int bfout) {
    constexpr int PW  = BK / 2 + 4;       // word pitch
    constexpr int CPR = BK / 8;           // 16B chunks per row
    constexpr int WM  = BM / 2;
    constexpr int WN  = BN / 4;
    constexpr int MT  = WM / 16;
    constexpr int NT  = WN / 8;
    constexpr int ACP = BM * CPR / 256;   // cp16 per thread per stage
    constexpr int BCP = BN * CPR / 256;

    extern __shared__ uint32_t smw[];
    uint32_t (*As)[BM][PW] = (uint32_t(*)[BM][PW])smw;
    uint32_t (*Bs)[BN][PW] = (uint32_t(*)[BN][PW])(smw + 2 * BM * PW);

    int tid  = threadIdx.x;
    int wid  = tid >> 5;
    int lane = tid & 31;
    int g    = lane >> 2;
    int cq   = lane & 3;
    int l15  = lane & 15;
    int h4   = (lane >> 4) * 4;
    int wm   = (wid & 1) * WM;
    int wn   = (wid >> 1) * WN;
    int r0   = blockIdx.y * BM;
    int c0   = blockIdx.x * BN;

    const uint16_t* Bseg;
    void* Cseg;
    int nseg, segc, segi;
    if (c0 < n0)           { Bseg = B0; Cseg = C0; nseg = n0; segc = c0; segi = 0; }
    else if (c0 < n0 + n1) { Bseg = B1; Cseg = C1; nseg = n1; segc = c0 - n0; segi = 1; }
    else                   { Bseg = B2; Cseg = C2; nseg = n2; segc = c0 - n0 - n1; segi = 2; }
    bool bfo = (bfout >> segi) & 1;

    float acc[MT][NT][4];
    #pragma unroll
    for (int t = 0; t < MT; t++)
        #pragma unroll
        for (int u = 0; u < NT; u++)
            #pragma unroll
            for (int i = 0; i < 4; i++) acc[t][u][i] = 0.0f;

    uint32_t aBase = s2u(&As[0][0][0]);
    uint32_t bBase = s2u(&Bs[0][0][0]);

    // stage 0
    #pragma unroll
    for (int t = 0; t < ACP; t++) {
        int idx = tid + t * 256;
        int ar = idx / CPR, ch = idx % CPR;
        cp16(s2u(&As[0][ar][ch * 4]), A + (size_t)(r0 + ar) * K + ch * 8);
    }
    #pragma unroll
    for (int t = 0; t < BCP; t++) {
        int idx = tid + t * 256;
        int br = idx / CPR, ch = idx % CPR;
        cp16(s2u(&Bs[0][br][ch * 4]), Bseg + (size_t)(segc + br) * K + ch * 8);
    }
    cp_commit();

    int NKB = K / BK;
    for (int kb = 0; kb < NKB; kb++) {
        int b = kb & 1;
        cp_wait<0>();
        __syncthreads();   // buffer kb ready; all warps done reading buf b^1

        if (kb + 1 < NKB) {
            int k0 = (kb + 1) * BK;
            #pragma unroll
            for (int t = 0; t < ACP; t++) {
                int idx = tid + t * 256;
                int ar = idx / CPR, ch = idx % CPR;
                cp16(s2u(&As[b ^ 1][ar][ch * 4]),
                     A + (size_t)(r0 + ar) * K + k0 + ch * 8);
            }
            #pragma unroll
            for (int t = 0; t < BCP; t++) {
                int idx = tid + t * 256;
                int br = idx / CPR, ch = idx % CPR;
                cp16(s2u(&Bs[b ^ 1][br][ch * 4]),
                     Bseg + (size_t)(segc + br) * K + k0 + ch * 8);
            }
            cp_commit();
        }

        uint32_t aB = aBase + (uint32_t)(b * BM * PW * 4);
        uint32_t bB = bBase + (uint32_t)(b * BN * PW * 4);

        #pragma unroll
        for (int k16 = 0; k16 < BK / 16; k16++) {
            int kw = k16 * 8 + h4;
            uint32_t af[MT][4];
            #pragma unroll
            for (int t = 0; t < MT; t++)
                ldsm_x4(af[t][0], af[t][1], af[t][2], af[t][3],
                        aB + (uint32_t)(((wm + 16 * t + l15) * PW + kw) * 4));
            uint32_t bf[NT][2];
            #pragma unroll
            for (int u2 = 0; u2 < NT / 2; u2++)
                ldsm_x4(bf[2 * u2][0], bf[2 * u2 + 1][0],
                        bf[2 * u2][1], bf[2 * u2 + 1][1],
                        bB + (uint32_t)(((wn + 16 * u2 + l15) * PW + kw) * 4));
            #pragma unroll
            for (int t = 0; t < MT; t++)
                #pragma unroll
                for (int u = 0; u < NT; u++)
                    mma_bf16(acc[t][u], af[t][0], af[t][1], af[t][2], af[t][3],
                             bf[u][0], bf[u][1]);
        }
    }

    #pragma unroll
    for (int t = 0; t < MT; t++) {
        int row = r0 + wm + 16 * t + g;
        #pragma unroll
        for (int u = 0; u < NT; u++) {
            int col = segc + wn + 8 * u + 2 * cq;
            size_t off0 = (size_t)row * nseg + col;
            size_t off1 = (size_t)(row + 8) * nseg + col;
            if (bfo) {
                uint16_t* Cb = (uint16_t*)Cseg;
                *(uint32_t*)(Cb + off0) = pack_bf16(acc[t][u][0], acc[t][u][1]);
                *(uint32_t*)(Cb + off1) = pack_bf16(acc[t][u][2], acc[t][u][3]);
            } else {
                float* Cf = (float*)Cseg;
                float2 r0v = make_float2(0.f, 0.f), r1v = make_float2(0.f, 0.f);
                if (R) {
                    r0v = *(const float2*)(R + off0);
                    r1v = *(const float2*)(R + off1);
                }
                *(float2*)(Cf + off0) = make_float2(acc[t][u][0] + r0v.x,
                                                    acc[t][u][1] + r0v.y);
                *(float2*)(Cf + off1) = make_float2(acc[t][u][2] + r1v.x,
                                                    acc[t][u][3] + r1v.y);
            }
        }
    }
}

// ---------------------------------------------------------------------------
// Fast RoPE + qk_norm on bf16 q/k: one block per s, 20 warps = 20 heads.
// Q scaled by 1/8 (exact pow2; folded softmax scale).
// ---------------------------------------------------------------------------
__global__ __launch_bounds__(640)
void rope_qknorm_fast(uint16_t* __restrict__ q, uint16_t* __restrict__ k,
                      float base) {
    __shared__ float scs[32], ssn[32];
    int s   = blockIdx.x;
    int tid = threadIdx.x;
    int w   = tid >> 5;
    int i   = tid & 31;

    if (tid < 32) {
        float invf = powf(base, -((float)(2 * tid) / (float)HDIM));
        float ang = (float)s * invf;
        sincosf(ang, &ssn[tid], &scs[tid]);
    }
    __syncthreads();

    uint32_t* p;
    float scale;
    if (w < NH) { p = (uint32_t*)(q + (size_t)s * DMODEL + w * HDIM); scale = 0.125f; }
    else        { p = (uint32_t*)(k + (size_t)s * LATD + (w - NH) * HDIM); scale = 1.0f; }

    uint32_t xw = p[i];
    float xe = bf_lo(xw), xo = bf_hi(xw);
    float cs = scs[i], sn = ssn[i];
    float re = xe * cs - xo * sn;
    float ro = xe * sn + xo * cs;

    float ss = re * re + ro * ro;
    #pragma unroll
    for (int o = 16; o > 0; o >>= 1)
        ss += __shfl_xor_sync(0xffffffffu, ss, o);

    float r = rsqrtf(ss / (float)HDIM + 1e-6f) * scale;
    p[i] = pack_bf16(re * r, ro * r);
}

// ---------------------------------------------------------------------------
// BF16 mma flash attention. Block = (64-q tile, head), 128 threads / 4 warps.
// cp.async double-buffered K/V (single sync per tile); ldmatrix K (non-trans)
// + V (trans); P stays in registers.
// SMEM words (pitch 36): Qs[64] Ks[2][64] Vs[2][64] = 46080 B
// ---------------------------------------------------------------------------
#define APW 36
__global__ __launch_bounds__(128, 3)
void fattn_mma(const uint16_t* __restrict__ Q, const uint16_t* __restrict__ K,
               const uint16_t* __restrict__ V, uint16_t* __restrict__ O,
               int win) {
    extern __shared__ uint32_t smw[];
    uint32_t (*Qs)[APW]     = (uint32_t(*)[APW])smw;
    uint32_t (*Ks)[64][APW] = (uint32_t(*)[64][APW])(smw + 64 * APW);
    uint32_t (*Vs)[64][APW] = (uint32_t(*)[64][APW])(smw + 3 * 64 * APW);

    int qt  = gridDim.x - 1 - blockIdx.x;   // heavy tiles first
    int h   = blockIdx.y;
    int kvh = h >> 2;
    int tid = threadIdx.x;
    int wid = tid >> 5;
    int lane = tid & 31;
    int g   = lane >> 2;
    int cq  = lane & 3;
    int l15 = lane & 15;
    int h4  = (lane >> 4) * 4;
    int m0  = wid * 16;
    int q0  = qt * 64;

    int jt0 = 0;
    if (win > 0) { jt0 = qt - 4; if (jt0 < 0) jt0 = 0; }

    // stage first K/V tile
    {
        int j0 = jt0 * 64;
        #pragma unroll
        for (int t = 0; t < 4; t++) {
            int idx = tid + t * 128;
            int jj = idx >> 3, ch = idx & 7;
            cp16(s2u(&Ks[0][jj][ch * 4]),
                 K + (size_t)(j0 + jj) * LATD + kvh * HDIM + ch * 8);
            cp16(s2u(&Vs[0][jj][ch * 4]),
                 V + (size_t)(j0 + jj) * LATD + kvh * HDIM + ch * 8);
        }
        cp_commit();
    }

    // stage Q (bf16, pre-scaled by 1/8)
    #pragma unroll
    for (int t = 0; t < 4; t++) {
        int idx = tid + t * 128;
        int qi = idx >> 3, ch = idx & 7;
        *(uint4*)&Qs[qi][ch * 4] =
            *(const uint4*)(Q + (size_t)(q0 + qi) * DMODEL + h * HDIM + ch * 8);
    }
    __syncthreads();

    // hoist Q fragments via ldmatrix (4 k16 windows over HDIM)
    uint32_t qBase = s2u(&Qs[0][0]);
    uint32_t qf[4][4];
    #pragma unroll
    for (int k16 = 0; k16 < 4; k16++)
        ldsm_x4(qf[k16][0], qf[k16][1], qf[k16][2], qf[k16][3],
                qBase + (uint32_t)(((m0 + l15) * APW + k16 * 8 + h4) * 4));

    float o[8][4];
    #pragma unroll
    for (int u = 0; u < 8; u++)
        #pragma unroll
        for (int i = 0; i < 4; i++) o[u][i] = 0.0f;
    float mrow0 = -60.0f, mrow1 = -60.0f;
    float lrow0 = 0.0f,   lrow1 = 0.0f;

    int row0 = q0 + m0 + g;
    int row1 = row0 + 8;
    uint32_t kBase = s2u(&Ks[0][0][0]);
    uint32_t vBase = s2u(&Vs[0][0][0]);

    for (int jt = jt0; jt <= qt; jt++) {
        int b = (jt - jt0) & 1;
        cp_wait<0>();
        __syncthreads();   // tile jt ready; all warps done reading buf b^1

        if (jt < qt) {
            int j0 = (jt + 1) * 64;
            #pragma unroll
            for (int t = 0; t < 4; t++) {
                int idx = tid + t * 128;
                int jj = idx >> 3, ch = idx & 7;
                cp16(s2u(&Ks[b ^ 1][jj][ch * 4]),
                     K + (size_t)(j0 + jj) * LATD + kvh * HDIM + ch * 8);
                cp16(s2u(&Vs[b ^ 1][jj][ch * 4]),
                     V + (size_t)(j0 + jj) * LATD + kvh * HDIM + ch * 8);
            }
            cp_commit();
        }

        int j0 = jt * 64;
        uint32_t kB = kBase + (uint32_t)(b * 64 * APW * 4);
        uint32_t vB = vBase + (uint32_t)(b * 64 * APW * 4);

        // S = Q K^T
        float s[8][4];
        #pragma unroll
        for (int u = 0; u < 8; u++)
            #pragma unroll
            for (int i = 0; i < 4; i++) s[u][i] = 0.0f;

        #pragma unroll
        for (int k16 = 0; k16 < 4; k16++) {
            int kw = k16 * 8 + h4;
            #pragma unroll
            for (int u2 = 0; u2 < 4; u2++) {
                uint32_t b00, b01, b10, b11;
                ldsm_x4(b00, b10, b01, b11,
                        kB + (uint32_t)(((u2 * 16 + l15) * APW + kw) * 4));
                mma_bf16(s[2 * u2],     qf[k16][0], qf[k16][1], qf[k16][2],
                         qf[k16][3], b00, b01);
                mma_bf16(s[2 * u2 + 1], qf[k16][0], qf[k16][1], qf[k16][2],
                         qf[k16][3], b10, b11);
            }
        }

        // mask
        #pragma unroll
        for (int u = 0; u < 8; u++) {
            int col = j0 + u * 8 + 2 * cq;
            #pragma unroll
            for (int i = 0; i < 4; i++) {
                int q  = (i < 2) ? row0 : row1;
                int kj = col + (i & 1);
                bool vis = (kj <= q) && (win == 0 || (q - kj) < win);
                if (!vis) s[u][i] = -1e30f;
            }
        }

        // online softmax
        float rm0 = -1e30f, rm1 = -1e30f;
        #pragma unroll
        for (int u = 0; u < 8; u++) {
            rm0 = fmaxf(rm0, fmaxf(s[u][0], s[u][1]));
            rm1 = fmaxf(rm1, fmaxf(s[u][2], s[u][3]));
        }
        #pragma unroll
        for (int off = 1; off <= 2; off <<= 1) {
            rm0 = fmaxf(rm0, __shfl_xor_sync(0xffffffffu, rm0, off));
            rm1 = fmaxf(rm1, __shfl_xor_sync(0xffffffffu, rm1, off));
        }
        float mn0 = fmaxf(mrow0, rm0);
        float mn1 = fmaxf(mrow1, rm1);
        float al0 = __expf(mrow0 - mn0);
        float al1 = __expf(mrow1 - mn1);
        float rs0 = 0.0f, rs1 = 0.0f;
        #pragma unroll
        for (int u = 0; u < 8; u++) {
            float p0 = __expf(s[u][0] - mn0);
            float p1 = __expf(s[u][1] - mn0);
            float p2 = __expf(s[u][2] - mn1);
            float p3 = __expf(s[u][3] - mn1);
            s[u][0] = p0; s[u][1] = p1; s[u][2] = p2; s[u][3] = p3;
            rs0 += p0 + p1;
            rs1 += p2 + p3;
        }
        #pragma unroll
        for (int off = 1; off <= 2; off <<= 1) {
            rs0 += __shfl_xor_sync(0xffffffffu, rs0, off);
            rs1 += __shfl_xor_sync(0xffffffffu, rs1, off);
        }
        lrow0 = lrow0 * al0 + rs0;
        lrow1 = lrow1 * al1 + rs1;
        mrow0 = mn0;
        mrow1 = mn1;
        #pragma unroll
        for (int u = 0; u < 8; u++) {
            o[u][0] *= al0; o[u][1] *= al0;
            o[u][2] *= al1; o[u][3] *= al1;
        }

        // P fragments directly from S accumulators (no SMEM round-trip)
        uint32_t pf[4][4];
        #pragma unroll
        for (int w = 0; w < 4; w++) {
            pf[w][0] = pack_bf16(s[2 * w][0],     s[2 * w][1]);
            pf[w][1] = pack_bf16(s[2 * w][2],     s[2 * w][3]);
            pf[w][2] = pack_bf16(s[2 * w + 1][0], s[2 * w + 1][1]);
            pf[w][3] = pack_bf16(s[2 * w + 1][2], s[2 * w + 1][3]);
        }

        // O += P @ V  (V trans-ldmatrix from [key][hd])
        #pragma unroll
        for (int w = 0; w < 4; w++) {
            #pragma unroll
            for (int u2 = 0; u2 < 4; u2++) {
                uint32_t c00, c01, c10, c11;
                ldsm_x4_t(c00, c01, c10, c11,
                          vB + (uint32_t)(((w * 16 + l15) * APW + u2 * 8 + h4) * 4));
                mma_bf16(o[2 * u2],     pf[w][0], pf[w][1], pf[w][2], pf[w][3],
                         c00, c01);
                mma_bf16(o[2 * u2 + 1], pf[w][0], pf[w][1], pf[w][2], pf[w][3],
                         c10, c11);
            }
        }
    }

    float inv0 = 1.0f / lrow0;
    float inv1 = 1.0f / lrow1;
    #pragma unroll
    for (int u = 0; u < 8; u++) {
        int col = u * 8 + 2 * cq;
        *(uint32_t*)(O + (size_t)row0 * DMODEL + h * HDIM + col) =
            pack_bf16(o[u][0] * inv0, o[u][1] * inv0);
        *(uint32_t*)(O + (size_t)row1 * DMODEL + h * HDIM + col) =
            pack_bf16(o[u][2] * inv1, o[u][3] * inv1);
    }
}

// ---------------------------------------------------------------------------
// Launch
// ---------------------------------------------------------------------------
extern "C" void kernel_launch(void* const* d_in, const int* in_sizes, int n_in,
                              void* d_out, int out_size) {
    (void)in_sizes; (void)n_in; (void)out_size;

    const float* hidden   = (const float*)d_in[0];
    const float* norm1_w  = (const float*)d_in[1];
    const float* norm2_w  = (const float*)d_in[2];
    const float* w_g_wq   = (const float*)d_in[3];
    const float* w_g_kvdn = (const float*)d_in[4];
    const float* w_g_k_up = (const float*)d_in[5];
    const float* w_g_v_up = (const float*)d_in[6];
    const float* w_g_wo   = (const float*)d_in[7];
    const float* w_l_wq   = (const float*)d_in[8];
    const float* w_l_wk   = (const float*)d_in[9];
    const float* w_l_wv   = (const float*)d_in[10];
    const float* w_l_wo   = (const float*)d_in[11];
    float* out = (float*)d_out;

    uint16_t *x1, *q, *lat, *k, *v, *attn, *gw;
    cudaGetSymbolAddress((void**)&x1,   g_x1);
    cudaGetSymbolAddress((void**)&q,    g_q);
    cudaGetSymbolAddress((void**)&lat,  g_lat);
    cudaGetSymbolAddress((void**)&k,    g_k);
    cudaGetSymbolAddress((void**)&v,    g_v);
    cudaGetSymbolAddress((void**)&attn, g_attn);
    cudaGetSymbolAddress((void**)&gw,   g_w);

    const int GEMM128_SMEM = 2 * (128 * 36 + 128 * 36) * 4;  // 73728 (BK=64)
    const int GEMM64_SMEM  = 2 * (64 * 36 + 64 * 36) * 4;    // 36864 (BK=64)
    const int ATTN_SMEM    = 5 * 64 * APW * 4;               // 46080

    cudaFuncSetAttribute(bgemm<128, 128, 64>,
                         cudaFuncAttributeMaxDynamicSharedMemorySize, GEMM128_SMEM);
    cudaFuncSetAttribute(bgemm<64, 64, 64>,
                         cudaFuncAttributeMaxDynamicSharedMemorySize, GEMM64_SMEM);
    cudaFuncSetAttribute(fattn_mma,
                         cudaFuncAttributeMaxDynamicSharedMemorySize, ATTN_SMEM);

    dim3 gridAttn(SEQ / 64, NH);   // (32, 16)

    // ---- Pre-pass: single fused weight transpose+convert ----
    transpose_all<<<4992, dim3(32, 8)>>>(gw,
        w_g_wq, w_g_kvdn, w_g_k_up, w_g_v_up, w_g_wo,
        w_l_wq, w_l_wk, w_l_wv, w_l_wo);

    // ---- Layer 1: global latent attention ----
    rmsnorm_kernel<<<SEQ, 256>>>(hidden, norm1_w, x1);
    bgemm<128, 128, 64><<<dim3(10, 16), 256, GEMM128_SMEM>>>(
        x1, gw + GWQ, q, DMODEL, gw + GKV, lat, LATD,
        nullptr, nullptr, 0, nullptr, DMODEL, /*bfout=*/3);
    bgemm<64, 64, 64><<<dim3(8, 32), 256, GEMM64_SMEM>>>(
        lat, gw + GKUP, k, LATD, gw + GVUP, v, LATD,
        nullptr, nullptr, 0, nullptr, LATD, /*bfout=*/3);
    rope_qknorm_fast<<<SEQ, 640>>>(q, k, 1000000.0f);
    fattn_mma<<<gridAttn, 128, ATTN_SMEM>>>(q, k, v, attn, /*win=*/0);
    bgemm<128, 128, 64><<<dim3(8, 16), 256, GEMM128_SMEM>>>(
        attn, gw + GWO, out, DMODEL, nullptr, nullptr, 0,
        nullptr, nullptr, 0, hidden, DMODEL, /*bfout=*/0);

    // ---- Layer 2: local GQA attention ----
    rmsnorm_kernel<<<SEQ, 256>>>(out, norm2_w, x1);
    bgemm<128, 128, 64><<<dim3(12, 16), 256, GEMM128_SMEM>>>(
        x1, gw + LWQ, q, DMODEL, gw + LWK, k, LATD,
        gw + LWV, v, LATD, nullptr, DMODEL, /*bfout=*/7);
    rope_qknorm_fast<<<SEQ, 640>>>(q, k, 10000.0f);
    fattn_mma<<<gridAttn, 128, ATTN_SMEM>>>(q, k, v, attn, /*win=*/WINSZ);
    bgemm<128, 128, 64><<<dim3(8, 16), 256, GEMM128_SMEM>>>(
        attn, gw + LWO, out, DMODEL, nullptr, nullptr, 0,
        nullptr, nullptr, 0, out, DMODEL, /*bfout=*/0);
}

// round 16
// speedup vs baseline: 1.2076x; 1.0314x over previous
#include <cuda_runtime.h>
#include <math.h>
#include <stdint.h>

#define SEQ    2048
#define DMODEL 1024
#define NH     16
#define NKVH   4
#define HDIM   64
#define LATD   256
#define WINSZ  256

// ---------------------------------------------------------------------------
// Scratch (device globals; no allocation allowed). Activations in bf16.
// ---------------------------------------------------------------------------
__device__ uint16_t g_x1  [SEQ * DMODEL];
__device__ uint16_t g_q   [SEQ * DMODEL];
__device__ uint16_t g_lat [SEQ * LATD];
__device__ uint16_t g_k   [SEQ * LATD];
__device__ uint16_t g_v   [SEQ * LATD];
__device__ uint16_t g_attn[SEQ * DMODEL];

// bf16 weights, TRANSPOSED to [N][K], concatenated (element offsets)
#define GWQ  0
#define GKV  1048576
#define GKUP 1310720
#define GVUP 1376256
#define GWO  1441792
#define LWQ  2490368
#define LWK  3538944
#define LWV  3801088
#define LWO  4063232
__device__ uint16_t g_w[5111808];

// ---------------------------------------------------------------------------
// Helpers
// ---------------------------------------------------------------------------
__device__ __forceinline__ uint16_t f2bf(float x) {
    uint16_t r;
    asm("cvt.rn.bf16.f32 %0, %1;" : "=h"(r) : "f"(x));
    return r;
}
__device__ __forceinline__ uint32_t pack_bf16(float lo, float hi) {
    uint32_t d;
    asm("cvt.rn.bf16x2.f32 %0, %1, %2;" : "=r"(d) : "f"(hi), "f"(lo));
    return d;
}
__device__ __forceinline__ float bf_lo(uint32_t w) { return __uint_as_float(w << 16); }
__device__ __forceinline__ float bf_hi(uint32_t w) { return __uint_as_float(w & 0xffff0000u); }

__device__ __forceinline__ void mma_bf16(float* c,
                                         uint32_t a0, uint32_t a1,
                                         uint32_t a2, uint32_t a3,
                                         uint32_t b0, uint32_t b1) {
    asm volatile(
        "mma.sync.aligned.m16n8k16.row.col.f32.bf16.bf16.f32 "
        "{%0,%1,%2,%3}, {%4,%5,%6,%7}, {%8,%9}, {%0,%1,%2,%3};\n"
        : "+f"(c[0]), "+f"(c[1]), "+f"(c[2]), "+f"(c[3])
        : "r"(a0), "r"(a1), "r"(a2), "r"(a3), "r"(b0), "r"(b1));
}

__device__ __forceinline__ void cp16(uint32_t s, const void* g) {
    asm volatile("cp.async.cg.shared.global [%0], [%1], 16;\n" :: "r"(s), "l"(g));
}
__device__ __forceinline__ void cp_commit() {
    asm volatile("cp.async.commit_group;\n");
}
template<int N>
__device__ __forceinline__ void cp_wait() {
    asm volatile("cp.async.wait_group %0;\n" :: "n"(N));
}
__device__ __forceinline__ uint32_t s2u(const void* p) {
    return (uint32_t)__cvta_generic_to_shared(p);
}
__device__ __forceinline__ void ldsm_x4(uint32_t& r0, uint32_t& r1,
                                        uint32_t& r2, uint32_t& r3, uint32_t a) {
    asm volatile("ldmatrix.sync.aligned.m8n8.x4.shared.b16 {%0,%1,%2,%3}, [%4];"
                 : "=r"(r0), "=r"(r1), "=r"(r2), "=r"(r3) : "r"(a));
}
__device__ __forceinline__ void ldsm_x4_t(uint32_t& r0, uint32_t& r1,
                                          uint32_t& r2, uint32_t& r3, uint32_t a) {
    asm volatile("ldmatrix.sync.aligned.m8n8.x4.trans.shared.b16 {%0,%1,%2,%3}, [%4];"
                 : "=r"(r0), "=r"(r1), "=r"(r2), "=r"(r3) : "r"(a));
}

// ---------------------------------------------------------------------------
// Fused weight transpose+bf16: one launch, 4992 tile-blocks over 9 segments.
// dst[n][k] = bf16(src[k][n])
// ---------------------------------------------------------------------------
__global__ void transpose_all(uint16_t* __restrict__ gw,
    const float* s0, const float* s1, const float* s2, const float* s3,
    const float* s4, const float* s5, const float* s6, const float* s7,
    const float* s8) {
    __shared__ float t[32][33];
    int tb = blockIdx.x;
    const float* src; uint16_t* dst; int K, N, tn;
    if (tb < 1024)      { src = s0; dst = gw + GWQ;  K = 1024; N = 1024; tn = tb; }
    else if (tb < 1280) { src = s1; dst = gw + GKV;  K = 1024; N = 256;  tn = tb - 1024; }
    else if (tb < 1344) { src = s2; dst = gw + GKUP; K = 256;  N = 256;  tn = tb - 1280; }
    else if (tb < 1408) { src = s3; dst = gw + GVUP; K = 256;  N = 256;  tn = tb - 1344; }
    else if (tb < 2432) { src = s4; dst = gw + GWO;  K = 1024; N = 1024; tn = tb - 1408; }
    else if (tb < 3456) { src = s5; dst = gw + LWQ;  K = 1024; N = 1024; tn = tb - 2432; }
    else if (tb < 3712) { src = s6; dst = gw + LWK;  K = 1024; N = 256;  tn = tb - 3456; }
    else if (tb < 3968) { src = s7; dst = gw + LWV;  K = 1024; N = 256;  tn = tb - 3712; }
    else                { src = s8; dst = gw + LWO;  K = 1024; N = 1024; tn = tb - 3968; }
    int tilesN = N >> 5;
    int n0 = (tn % tilesN) * 32, k0 = (tn / tilesN) * 32;
    int x = threadIdx.x, y = threadIdx.y;
    #pragma unroll
    for (int i = 0; i < 32; i += 8)
        t[y + i][x] = src[(size_t)(k0 + y + i) * N + n0 + x];
    __syncthreads();
    #pragma unroll
    for (int i = 0; i < 32; i += 8)
        dst[(size_t)(n0 + y + i) * K + k0 + x] = f2bf(t[x][y + i]);
}

// ---------------------------------------------------------------------------
// RMSNorm: fp32 in -> bf16 out
// ---------------------------------------------------------------------------
__global__ void rmsnorm_kernel(const float* __restrict__ x,
                               const float* __restrict__ w,
                               uint16_t* __restrict__ y) {
    int row = blockIdx.x;
    int tid = threadIdx.x;
    const float4* xr = (const float4*)(x + (size_t)row * DMODEL);
    float4 v = xr[tid];
    float ss = v.x * v.x + v.y * v.y + v.z * v.z + v.w * v.w;
    __shared__ float red[256];
    red[tid] = ss;
    __syncthreads();
    #pragma unroll
    for (int o = 128; o > 0; o >>= 1) {
        if (tid < o) red[tid] += red[tid + o];
        __syncthreads();
    }
    float r = rsqrtf(red[0] / (float)DMODEL + 1e-6f);
    float4 wv = ((const float4*)w)[tid];
    uint32_t* yw = (uint32_t*)(y + (size_t)row * DMODEL);
    yw[2 * tid]     = pack_bf16(v.x * r * wv.x, v.y * r * wv.y);
    yw[2 * tid + 1] = pack_bf16(v.z * r * wv.z, v.w * r * wv.w);
}

// ---------------------------------------------------------------------------
// Segmented BF16 GEMM: cp.async double-buffered (single sync per k-block) +
// ldmatrix fragments. A bf16 [M][K]; B bf16 [nseg][K] (pre-transposed);
// warp layout 2m x 4n.
// ---------------------------------------------------------------------------
template<int BM, int BN, int BK>
__global__ __launch_bounds__(256, 2)
void bgemm(const uint16_t* __restrict__ A,
           const uint16_t* __restrict__ B0, void* C0, int n0,
           const uint16_t* __restrict__ B1, void* C1, int n1,
           const uint16_t* __restrict__ B2, void* C2, int n2,
           const float* __restrict__ R, int K, int bfout) {
    constexpr int PW  = BK / 2 + 4;       // word pitch
    constexpr int CPR = BK / 8;           // 16B chunks per row
    constexpr int WM  = BM / 2;
    constexpr int WN  = BN / 4;
    constexpr int MT  = WM / 16;
    constexpr int NT  = WN / 8;
    constexpr int ACP = BM * CPR / 256;   // cp16 per thread per stage
    constexpr int BCP = BN * CPR / 256;

    extern __shared__ uint32_t smw[];
    uint32_t (*As)[BM][PW] = (uint32_t(*)[BM][PW])smw;
    uint32_t (*Bs)[BN][PW] = (uint32_t(*)[BN][PW])(smw + 2 * BM * PW);

    int tid  = threadIdx.x;
    int wid  = tid >> 5;
    int lane = tid & 31;
    int g    = lane >> 2;
    int cq   = lane & 3;
    int l15  = lane & 15;
    int h4   = (lane >> 4) * 4;
    int wm   = (wid & 1) * WM;
    int wn   = (wid >> 1) * WN;
    int r0   = blockIdx.y * BM;
    int c0   = blockIdx.x * BN;

    const uint16_t* Bseg;
    void* Cseg;
    int nseg, segc, segi;
    if (c0 < n0)           { Bseg = B0; Cseg = C0; nseg = n0; segc = c0; segi = 0; }
    else if (c0 < n0 + n1) { Bseg = B1; Cseg = C1; nseg = n1; segc = c0 - n0; segi = 1; }
    else                   { Bseg = B2; Cseg = C2; nseg = n2; segc = c0 - n0 - n1; segi = 2; }
    bool bfo = (bfout >> segi) & 1;

    float acc[MT][NT][4];
    #pragma unroll
    for (int t = 0; t < MT; t++)
        #pragma unroll
        for (int u = 0; u < NT; u++)
            #pragma unroll
            for (int i = 0; i < 4; i++) acc[t][u][i] = 0.0f;

    uint32_t aBase = s2u(&As[0][0][0]);
    uint32_t bBase = s2u(&Bs[0][0][0]);

    // stage 0
    #pragma unroll
    for (int t = 0; t < ACP; t++) {
        int idx = tid + t * 256;
        int ar = idx / CPR, ch = idx % CPR;
        cp16(s2u(&As[0][ar][ch * 4]), A + (size_t)(r0 + ar) * K + ch * 8);
    }
    #pragma unroll
    for (int t = 0; t < BCP; t++) {
        int idx = tid + t * 256;
        int br = idx / CPR, ch = idx % CPR;
        cp16(s2u(&Bs[0][br][ch * 4]), Bseg + (size_t)(segc + br) * K + ch * 8);
    }
    cp_commit();

    int NKB = K / BK;
    for (int kb = 0; kb < NKB; kb++) {
        int b = kb & 1;
        cp_wait<0>();
        __syncthreads();   // buffer kb ready; all warps done reading buf b^1

        if (kb + 1 < NKB) {
            int k0 = (kb + 1) * BK;
            #pragma unroll
            for (int t = 0; t < ACP; t++) {
                int idx = tid + t * 256;
                int ar = idx / CPR, ch = idx % CPR;
                cp16(s2u(&As[b ^ 1][ar][ch * 4]),
                     A + (size_t)(r0 + ar) * K + k0 + ch * 8);
            }
            #pragma unroll
            for (int t = 0; t < BCP; t++) {
                int idx = tid + t * 256;
                int br = idx / CPR, ch = idx % CPR;
                cp16(s2u(&Bs[b ^ 1][br][ch * 4]),
                     Bseg + (size_t)(segc + br) * K + k0 + ch * 8);
            }
            cp_commit();
        }

        uint32_t aB = aBase + (uint32_t)(b * BM * PW * 4);
        uint32_t bB = bBase + (uint32_t)(b * BN * PW * 4);

        #pragma unroll
        for (int k16 = 0; k16 < BK / 16; k16++) {
            int kw = k16 * 8 + h4;
            uint32_t af[MT][4];
            #pragma unroll
            for (int t = 0; t < MT; t++)
                ldsm_x4(af[t][0], af[t][1], af[t][2], af[t][3],
                        aB + (uint32_t)(((wm + 16 * t + l15) * PW + kw) * 4));
            uint32_t bf[NT][2];
            #pragma unroll
            for (int u2 = 0; u2 < NT / 2; u2++)
                ldsm_x4(bf[2 * u2][0], bf[2 * u2 + 1][0],
                        bf[2 * u2][1], bf[2 * u2 + 1][1],
                        bB + (uint32_t)(((wn + 16 * u2 + l15) * PW + kw) * 4));
            #pragma unroll
            for (int t = 0; t < MT; t++)
                #pragma unroll
                for (int u = 0; u < NT; u++)
                    mma_bf16(acc[t][u], af[t][0], af[t][1], af[t][2], af[t][3],
                             bf[u][0], bf[u][1]);
        }
    }

    #pragma unroll
    for (int t = 0; t < MT; t++) {
        int row = r0 + wm + 16 * t + g;
        #pragma unroll
        for (int u = 0; u < NT; u++) {
            int col = segc + wn + 8 * u + 2 * cq;
            size_t off0 = (size_t)row * nseg + col;
            size_t off1 = (size_t)(row + 8) * nseg + col;
            if (bfo) {
                uint16_t* Cb = (uint16_t*)Cseg;
                *(uint32_t*)(Cb + off0) = pack_bf16(acc[t][u][0], acc[t][u][1]);
                *(uint32_t*)(Cb + off1) = pack_bf16(acc[t][u][2], acc[t][u][3]);
            } else {
                float* Cf = (float*)Cseg;
                float2 r0v = make_float2(0.f, 0.f), r1v = make_float2(0.f, 0.f);
                if (R) {
                    r0v = *(const float2*)(R + off0);
                    r1v = *(const float2*)(R + off1);
                }
                *(float2*)(Cf + off0) = make_float2(acc[t][u][0] + r0v.x,
                                                    acc[t][u][1] + r0v.y);
                *(float2*)(Cf + off1) = make_float2(acc[t][u][2] + r1v.x,
                                                    acc[t][u][3] + r1v.y);
            }
        }
    }
}

// ---------------------------------------------------------------------------
// Fast RoPE + qk_norm on bf16 q/k: one block per s, 20 warps = 20 heads.
// Q scaled by 1/8 (exact pow2; folded softmax scale).
// ---------------------------------------------------------------------------
__global__ __launch_bounds__(640)
void rope_qknorm_fast(uint16_t* __restrict__ q, uint16_t* __restrict__ k,
                      float base) {
    __shared__ float scs[32], ssn[32];
    int s   = blockIdx.x;
    int tid = threadIdx.x;
    int w   = tid >> 5;
    int i   = tid & 31;

    if (tid < 32) {
        float invf = powf(base, -((float)(2 * tid) / (float)HDIM));
        float ang = (float)s * invf;
        sincosf(ang, &ssn[tid], &scs[tid]);
    }
    __syncthreads();

    uint32_t* p;
    float scale;
    if (w < NH) { p = (uint32_t*)(q + (size_t)s * DMODEL + w * HDIM); scale = 0.125f; }
    else        { p = (uint32_t*)(k + (size_t)s * LATD + (w - NH) * HDIM); scale = 1.0f; }

    uint32_t xw = p[i];
    float xe = bf_lo(xw), xo = bf_hi(xw);
    float cs = scs[i], sn = ssn[i];
    float re = xe * cs - xo * sn;
    float ro = xe * sn + xo * cs;

    float ss = re * re + ro * ro;
    #pragma unroll
    for (int o = 16; o > 0; o >>= 1)
        ss += __shfl_xor_sync(0xffffffffu, ss, o);

    float r = rsqrtf(ss / (float)HDIM + 1e-6f) * scale;
    p[i] = pack_bf16(re * r, ro * r);
}

// ---------------------------------------------------------------------------
// BF16 mma flash attention. Block = (64-q tile, head), 128 threads / 4 warps.
// Scores bounded in [-8, 8] by qk_norm + folded 1/8 scale, so softmax uses a
// FIXED max of 8.0: no running max, no rescale of the O accumulator.
// cp.async double-buffered K/V (single sync per tile); ldmatrix K + V(trans);
// P stays in registers. SMEM words (pitch 36): Qs[64] Ks[2][64] Vs[2][64].
// ---------------------------------------------------------------------------
#define APW 36
__global__ __launch_bounds__(128, 3)
void fattn_mma(const uint16_t* __restrict__ Q, const uint16_t* __restrict__ K,
               const uint16_t* __restrict__ V, uint16_t* __restrict__ O,
               int win) {
    extern __shared__ uint32_t smw[];
    uint32_t (*Qs)[APW]     = (uint32_t(*)[APW])smw;
    uint32_t (*Ks)[64][APW] = (uint32_t(*)[64][APW])(smw + 64 * APW);
    uint32_t (*Vs)[64][APW] = (uint32_t(*)[64][APW])(smw + 3 * 64 * APW);

    int qt  = gridDim.x - 1 - blockIdx.x;   // heavy tiles first
    int h   = blockIdx.y;
    int kvh = h >> 2;
    int tid = threadIdx.x;
    int wid = tid >> 5;
    int lane = tid & 31;
    int g   = lane >> 2;
    int cq  = lane & 3;
    int l15 = lane & 15;
    int h4  = (lane >> 4) * 4;
    int m0  = wid * 16;
    int q0  = qt * 64;

    int jt0 = 0;
    if (win > 0) { jt0 = qt - 4; if (jt0 < 0) jt0 = 0; }

    // stage first K/V tile
    {
        int j0 = jt0 * 64;
        #pragma unroll
        for (int t = 0; t < 4; t++) {
            int idx = tid + t * 128;
            int jj = idx >> 3, ch = idx & 7;
            cp16(s2u(&Ks[0][jj][ch * 4]),
                 K + (size_t)(j0 + jj) * LATD + kvh * HDIM + ch * 8);
            cp16(s2u(&Vs[0][jj][ch * 4]),
                 V + (size_t)(j0 + jj) * LATD + kvh * HDIM + ch * 8);
        }
        cp_commit();
    }

    // stage Q (bf16, pre-scaled by 1/8)
    #pragma unroll
    for (int t = 0; t < 4; t++) {
        int idx = tid + t * 128;
        int qi = idx >> 3, ch = idx & 7;
        *(uint4*)&Qs[qi][ch * 4] =
            *(const uint4*)(Q + (size_t)(q0 + qi) * DMODEL + h * HDIM + ch * 8);
    }
    __syncthreads();

    // hoist Q fragments via ldmatrix (4 k16 windows over HDIM)
    uint32_t qBase = s2u(&Qs[0][0]);
    uint32_t qf[4][4];
    #pragma unroll
    for (int k16 = 0; k16 < 4; k16++)
        ldsm_x4(qf[k16][0], qf[k16][1], qf[k16][2], qf[k16][3],
                qBase + (uint32_t)(((m0 + l15) * APW + k16 * 8 + h4) * 4));

    float o[8][4];
    #pragma unroll
    for (int u = 0; u < 8; u++)
        #pragma unroll
        for (int i = 0; i < 4; i++) o[u][i] = 0.0f;
    float lrow0 = 0.0f, lrow1 = 0.0f;

    int row0 = q0 + m0 + g;
    int row1 = row0 + 8;
    uint32_t kBase = s2u(&Ks[0][0][0]);
    uint32_t vBase = s2u(&Vs[0][0][0]);

    for (int jt = jt0; jt <= qt; jt++) {
        int b = (jt - jt0) & 1;
        cp_wait<0>();
        __syncthreads();   // tile jt ready; all warps done reading buf b^1

        if (jt < qt) {
            int j0 = (jt + 1) * 64;
            #pragma unroll
            for (int t = 0; t < 4; t++) {
                int idx = tid + t * 128;
                int jj = idx >> 3, ch = idx & 7;
                cp16(s2u(&Ks[b ^ 1][jj][ch * 4]),
                     K + (size_t)(j0 + jj) * LATD + kvh * HDIM + ch * 8);
                cp16(s2u(&Vs[b ^ 1][jj][ch * 4]),
                     V + (size_t)(j0 + jj) * LATD + kvh * HDIM + ch * 8);
            }
            cp_commit();
        }

        int j0 = jt * 64;
        uint32_t kB = kBase + (uint32_t)(b * 64 * APW * 4);
        uint32_t vB = vBase + (uint32_t)(b * 64 * APW * 4);

        // S = Q K^T
        float s[8][4];
        #pragma unroll
        for (int u = 0; u < 8; u++)
            #pragma unroll
            for (int i = 0; i < 4; i++) s[u][i] = 0.0f;

        #pragma unroll
        for (int k16 = 0; k16 < 4; k16++) {
            int kw = k16 * 8 + h4;
            #pragma unroll
            for (int u2 = 0; u2 < 4; u2++) {
                uint32_t b00, b01, b10, b11;
                ldsm_x4(b00, b10, b01, b11,
                        kB + (uint32_t)(((u2 * 16 + l15) * APW + kw) * 4));
                mma_bf16(s[2 * u2],     qf[k16][0], qf[k16][1], qf[k16][2],
                         qf[k16][3], b00, b01);
                mma_bf16(s[2 * u2 + 1], qf[k16][0], qf[k16][1], qf[k16][2],
                         qf[k16][3], b10, b11);
            }
        }

        // mask (skipped for interior fully-visible tiles)
        bool fullvis = (jt < qt) && (win == 0 || (q0 + 63 - j0) < win);
        if (!fullvis) {
            #pragma unroll
            for (int u = 0; u < 8; u++) {
                int col = j0 + u * 8 + 2 * cq;
                #pragma unroll
                for (int i = 0; i < 4; i++) {
                    int q  = (i < 2) ? row0 : row1;
                    int kj = col + (i & 1);
                    bool vis = (kj <= q) && (win == 0 || (q - kj) < win);
                    if (!vis) s[u][i] = -1e30f;
                }
            }
        }

        // softmax with FIXED max = 8 (scores bounded by qk_norm)
        float rs0 = 0.0f, rs1 = 0.0f;
        #pragma unroll
        for (int u = 0; u < 8; u++) {
            float p0 = __expf(s[u][0] - 8.0f);
            float p1 = __expf(s[u][1] - 8.0f);
            float p2 = __expf(s[u][2] - 8.0f);
            float p3 = __expf(s[u][3] - 8.0f);
            s[u][0] = p0; s[u][1] = p1; s[u][2] = p2; s[u][3] = p3;
            rs0 += p0 + p1;
            rs1 += p2 + p3;
        }
        #pragma unroll
        for (int off = 1; off <= 2; off <<= 1) {
            rs0 += __shfl_xor_sync(0xffffffffu, rs0, off);
            rs1 += __shfl_xor_sync(0xffffffffu, rs1, off);
        }
        lrow0 += rs0;
        lrow1 += rs1;

        // P fragments directly from S accumulators (no SMEM round-trip)
        uint32_t pf[4][4];
        #pragma unroll
        for (int w = 0; w < 4; w++) {
            pf[w][0] = pack_bf16(s[2 * w][0],     s[2 * w][1]);
            pf[w][1] = pack_bf16(s[2 * w][2],     s[2 * w][3]);
            pf[w][2] = pack_bf16(s[2 * w + 1][0], s[2 * w + 1][1]);
            pf[w][3] = pack_bf16(s[2 * w + 1][2], s[2 * w + 1][3]);
        }

        // O += P @ V  (V trans-ldmatrix from [key][hd])
        #pragma unroll
        for (int w = 0; w < 4; w++) {
            #pragma unroll
            for (int u2 = 0; u2 < 4; u2++) {
                uint32_t c00, c01, c10, c11;
                ldsm_x4_t(c00, c01, c10, c11,
                          vB + (uint32_t)(((w * 16 + l15) * APW + u2 * 8 + h4) * 4));
                mma_bf16(o[2 * u2],     pf[w][0], pf[w][1], pf[w][2], pf[w][3],
                         c00, c01);
                mma_bf16(o[2 * u2 + 1], pf[w][0], pf[w][1], pf[w][2], pf[w][3],
                         c10, c11);
            }
        }
    }

    float inv0 = 1.0f / lrow0;
    float inv1 = 1.0f / lrow1;
    #pragma unroll
    for (int u = 0; u < 8; u++) {
        int col = u * 8 + 2 * cq;
        *(uint32_t*)(O + (size_t)row0 * DMODEL + h * HDIM + col) =
            pack_bf16(o[u][0] * inv0, o[u][1] * inv0);
        *(uint32_t*)(O + (size_t)row1 * DMODEL + h * HDIM + col) =
            pack_bf16(o[u][2] * inv1, o[u][3] * inv1);
    }
}

// ---------------------------------------------------------------------------
// Launch
// ---------------------------------------------------------------------------
extern "C" void kernel_launch(void* const* d_in, const int* in_sizes, int n_in,
                              void* d_out, int out_size) {
    (void)in_sizes; (void)n_in; (void)out_size;

    const float* hidden   = (const float*)d_in[0];
    const float* norm1_w  = (const float*)d_in[1];
    const float* norm2_w  = (const float*)d_in[2];
    const float* w_g_wq   = (const float*)d_in[3];
    const float* w_g_kvdn = (const float*)d_in[4];
    const float* w_g_k_up = (const float*)d_in[5];
    const float* w_g_v_up = (const float*)d_in[6];
    const float* w_g_wo   = (const float*)d_in[7];
    const float* w_l_wq   = (const float*)d_in[8];
    const float* w_l_wk   = (const float*)d_in[9];
    const float* w_l_wv   = (const float*)d_in[10];
    const float* w_l_wo   = (const float*)d_in[11];
    float* out = (float*)d_out;

    uint16_t *x1, *q, *lat, *k, *v, *attn, *gw;
    cudaGetSymbolAddress((void**)&x1,   g_x1);
    cudaGetSymbolAddress((void**)&q,    g_q);
    cudaGetSymbolAddress((void**)&lat,  g_lat);
    cudaGetSymbolAddress((void**)&k,    g_k);
    cudaGetSymbolAddress((void**)&v,    g_v);
    cudaGetSymbolAddress((void**)&attn, g_attn);
    cudaGetSymbolAddress((void**)&gw,   g_w);

    const int GEMM128_SMEM = 2 * (128 * 36 + 128 * 36) * 4;  // 73728 (BK=64)
    const int GEMM64_SMEM  = 2 * (64 * 36 + 64 * 36) * 4;    // 36864 (BK=64)
    const int ATTN_SMEM    = 5 * 64 * APW * 4;               // 46080

    cudaFuncSetAttribute(bgemm<128, 128, 64>,
                         cudaFuncAttributeMaxDynamicSharedMemorySize, GEMM128_SMEM);
    cudaFuncSetAttribute(bgemm<64, 64, 64>,
                         cudaFuncAttributeMaxDynamicSharedMemorySize, GEMM64_SMEM);
    cudaFuncSetAttribute(fattn_mma,
                         cudaFuncAttributeMaxDynamicSharedMemorySize, ATTN_SMEM);

    dim3 gridAttn(SEQ / 64, NH);   // (32, 16)

    // ---- Pre-pass: single fused weight transpose+convert ----
    transpose_all<<<4992, dim3(32, 8)>>>(gw,
        w_g_wq, w_g_kvdn, w_g_k_up, w_g_v_up, w_g_wo,
        w_l_wq, w_l_wk, w_l_wv, w_l_wo);

    // ---- Layer 1: global latent attention ----
    rmsnorm_kernel<<<SEQ, 256>>>(hidden, norm1_w, x1);
    bgemm<128, 128, 64><<<dim3(10, 16), 256, GEMM128_SMEM>>>(
        x1, gw + GWQ, q, DMODEL, gw + GKV, lat, LATD,
        nullptr, nullptr, 0, nullptr, DMODEL, /*bfout=*/3);
    bgemm<64, 64, 64><<<dim3(8, 32), 256, GEMM64_SMEM>>>(
        lat, gw + GKUP, k, LATD, gw + GVUP, v, LATD,
        nullptr, nullptr, 0, nullptr, LATD, /*bfout=*/3);
    rope_qknorm_fast<<<SEQ, 640>>>(q, k, 1000000.0f);
    fattn_mma<<<gridAttn, 128, ATTN_SMEM>>>(q, k, v, attn, /*win=*/0);
    bgemm<128, 128, 64><<<dim3(8, 16), 256, GEMM128_SMEM>>>(
        attn, gw + GWO, out, DMODEL, nullptr, nullptr, 0,
        nullptr, nullptr, 0, hidden, DMODEL, /*bfout=*/0);

    // ---- Layer 2: local GQA attention ----
    rmsnorm_kernel<<<SEQ, 256>>>(out, norm2_w, x1);
    bgemm<128, 128, 64><<<dim3(12, 16), 256, GEMM128_SMEM>>>(
        x1, gw + LWQ, q, DMODEL, gw + LWK, k, LATD,
        gw + LWV, v, LATD, nullptr, DMODEL, /*bfout=*/7);
    rope_qknorm_fast<<<SEQ, 640>>>(q, k, 10000.0f);
    fattn_mma<<<gridAttn, 128, ATTN_SMEM>>>(q, k, v, attn, /*win=*/WINSZ);
    bgemm<128, 128, 64><<<dim3(8, 16), 256, GEMM128_SMEM>>>(
        attn, gw + LWO, out, DMODEL, nullptr, nullptr, 0,
        nullptr, nullptr, 0, out, DMODEL, /*bfout=*/0);
}

// round 17
// speedup vs baseline: 1.2140x; 1.0053x over previous
#include <cuda_runtime.h>
#include <math.h>
#include <stdint.h>

#define SEQ    2048
#define DMODEL 1024
#define NH     16
#define NKVH   4
#define HDIM   64
#define LATD   256
#define WINSZ  256

// ---------------------------------------------------------------------------
// Scratch (device globals; no allocation allowed). Activations in bf16.
// ---------------------------------------------------------------------------
__device__ uint16_t g_x1  [SEQ * DMODEL];
__device__ uint16_t g_q   [SEQ * DMODEL];
__device__ uint16_t g_lat [SEQ * LATD];
__device__ uint16_t g_k   [SEQ * LATD];
__device__ uint16_t g_v   [SEQ * LATD];
__device__ uint16_t g_attn[SEQ * DMODEL];

// bf16 weights, TRANSPOSED to [N][K], concatenated (element offsets)
#define GWQ  0
#define GKV  1048576
#define GKUP 1310720
#define GVUP 1376256
#define GWO  1441792
#define LWQ  2490368
#define LWK  3538944
#define LWV  3801088
#define LWO  4063232
__device__ uint16_t g_w[5111808];

// ---------------------------------------------------------------------------
// Helpers
// ---------------------------------------------------------------------------
__device__ __forceinline__ uint16_t f2bf(float x) {
    uint16_t r;
    asm("cvt.rn.bf16.f32 %0, %1;" : "=h"(r) : "f"(x));
    return r;
}
__device__ __forceinline__ uint32_t pack_bf16(float lo, float hi) {
    uint32_t d;
    asm("cvt.rn.bf16x2.f32 %0, %1, %2;" : "=r"(d) : "f"(hi), "f"(lo));
    return d;
}
__device__ __forceinline__ float bf_lo(uint32_t w) { return __uint_as_float(w << 16); }
__device__ __forceinline__ float bf_hi(uint32_t w) { return __uint_as_float(w & 0xffff0000u); }

__device__ __forceinline__ void mma_bf16(float* c,
                                         uint32_t a0, uint32_t a1,
                                         uint32_t a2, uint32_t a3,
                                         uint32_t b0, uint32_t b1) {
    asm volatile(
        "mma.sync.aligned.m16n8k16.row.col.f32.bf16.bf16.f32 "
        "{%0,%1,%2,%3}, {%4,%5,%6,%7}, {%8,%9}, {%0,%1,%2,%3};\n"
        : "+f"(c[0]), "+f"(c[1]), "+f"(c[2]), "+f"(c[3])
        : "r"(a0), "r"(a1), "r"(a2), "r"(a3), "r"(b0), "r"(b1));
}

__device__ __forceinline__ void cp16(uint32_t s, const void* g) {
    asm volatile("cp.async.cg.shared.global [%0], [%1], 16;\n" :: "r"(s), "l"(g));
}
__device__ __forceinline__ void cp_commit() {
    asm volatile("cp.async.commit_group;\n");
}
template<int N>
__device__ __forceinline__ void cp_wait() {
    asm volatile("cp.async.wait_group %0;\n" :: "n"(N));
}
__device__ __forceinline__ uint32_t s2u(const void* p) {
    return (uint32_t)__cvta_generic_to_shared(p);
}
__device__ __forceinline__ void ldsm_x4(uint32_t& r0, uint32_t& r1,
                                        uint32_t& r2, uint32_t& r3, uint32_t a) {
    asm volatile("ldmatrix.sync.aligned.m8n8.x4.shared.b16 {%0,%1,%2,%3}, [%4];"
                 : "=r"(r0), "=r"(r1), "=r"(r2), "=r"(r3) : "r"(a));
}
__device__ __forceinline__ void ldsm_x4_t(uint32_t& r0, uint32_t& r1,
                                          uint32_t& r2, uint32_t& r3, uint32_t a) {
    asm volatile("ldmatrix.sync.aligned.m8n8.x4.trans.shared.b16 {%0,%1,%2,%3}, [%4];"
                 : "=r"(r0), "=r"(r1), "=r"(r2), "=r"(r3) : "r"(a));
}

// ---------------------------------------------------------------------------
// Fused prep: weight transpose+bf16 (4992 tile-blocks) ++ layer-1 rmsnorm
// (2048 row-blocks). 256 threads.  dst[n][k] = bf16(src[k][n]).
// ---------------------------------------------------------------------------
__global__ __launch_bounds__(256)
void prep_kernel(uint16_t* __restrict__ gw,
    const float* s0, const float* s1, const float* s2, const float* s3,
    const float* s4, const float* s5, const float* s6, const float* s7,
    const float* s8,
    const float* __restrict__ hidden, const float* __restrict__ norm1_w,
    uint16_t* __restrict__ x1) {
    __shared__ float t[1056];   // 32x33 transpose tile / 256-float reduction
    int tb = blockIdx.x;
    int tid = threadIdx.x;

    if (tb < 4992) {
        const float* src; uint16_t* dst; int K, N, tn;
        if (tb < 1024)      { src = s0; dst = gw + GWQ;  K = 1024; N = 1024; tn = tb; }
        else if (tb < 1280) { src = s1; dst = gw + GKV;  K = 1024; N = 256;  tn = tb - 1024; }
        else if (tb < 1344) { src = s2; dst = gw + GKUP; K = 256;  N = 256;  tn = tb - 1280; }
        else if (tb < 1408) { src = s3; dst = gw + GVUP; K = 256;  N = 256;  tn = tb - 1344; }
        else if (tb < 2432) { src = s4; dst = gw + GWO;  K = 1024; N = 1024; tn = tb - 1408; }
        else if (tb < 3456) { src = s5; dst = gw + LWQ;  K = 1024; N = 1024; tn = tb - 2432; }
        else if (tb < 3712) { src = s6; dst = gw + LWK;  K = 1024; N = 256;  tn = tb - 3456; }
        else if (tb < 3968) { src = s7; dst = gw + LWV;  K = 1024; N = 256;  tn = tb - 3712; }
        else                { src = s8; dst = gw + LWO;  K = 1024; N = 1024; tn = tb - 3968; }
        int tilesN = N >> 5;
        int n0 = (tn % tilesN) * 32, k0 = (tn / tilesN) * 32;
        int x = tid & 31, y = tid >> 5;
        #pragma unroll
        for (int i = 0; i < 32; i += 8)
            t[(y + i) * 33 + x] = src[(size_t)(k0 + y + i) * N + n0 + x];
        __syncthreads();
        #pragma unroll
        for (int i = 0; i < 32; i += 8)
            dst[(size_t)(n0 + y + i) * K + k0 + x] = f2bf(t[x * 33 + y + i]);
    } else {
        int row = tb - 4992;
        const float4* xr = (const float4*)(hidden + (size_t)row * DMODEL);
        float4 v = xr[tid];
        float ss = v.x * v.x + v.y * v.y + v.z * v.z + v.w * v.w;
        t[tid] = ss;
        __syncthreads();
        #pragma unroll
        for (int o = 128; o > 0; o >>= 1) {
            if (tid < o) t[tid] += t[tid + o];
            __syncthreads();
        }
        float r = rsqrtf(t[0] / (float)DMODEL + 1e-6f);
        float4 wv = ((const float4*)norm1_w)[tid];
        uint32_t* yw = (uint32_t*)(x1 + (size_t)row * DMODEL);
        yw[2 * tid]     = pack_bf16(v.x * r * wv.x, v.y * r * wv.y);
        yw[2 * tid + 1] = pack_bf16(v.z * r * wv.z, v.w * r * wv.w);
    }
}

// ---------------------------------------------------------------------------
// RMSNorm: fp32 in -> bf16 out (layer 2)
// ---------------------------------------------------------------------------
__global__ void rmsnorm_kernel(const float* __restrict__ x,
                               const float* __restrict__ w,
                               uint16_t* __restrict__ y) {
    int row = blockIdx.x;
    int tid = threadIdx.x;
    const float4* xr = (const float4*)(x + (size_t)row * DMODEL);
    float4 v = xr[tid];
    float ss = v.x * v.x + v.y * v.y + v.z * v.z + v.w * v.w;
    __shared__ float red[256];
    red[tid] = ss;
    __syncthreads();
    #pragma unroll
    for (int o = 128; o > 0; o >>= 1) {
        if (tid < o) red[tid] += red[tid + o];
        __syncthreads();
    }
    float r = rsqrtf(red[0] / (float)DMODEL + 1e-6f);
    float4 wv = ((const float4*)w)[tid];
    uint32_t* yw = (uint32_t*)(y + (size_t)row * DMODEL);
    yw[2 * tid]     = pack_bf16(v.x * r * wv.x, v.y * r * wv.y);
    yw[2 * tid + 1] = pack_bf16(v.z * r * wv.z, v.w * r * wv.w);
}

// ---------------------------------------------------------------------------
// Segmented BF16 GEMM: cp.async double-buffered (single sync per k-block) +
// ldmatrix fragments. A bf16 [M][K]; B bf16 [nseg][K] (pre-transposed);
// warp layout 2m x 4n.
// ---------------------------------------------------------------------------
template<int BM, int BN, int BK>
__global__ __launch_bounds__(256, 2)
void bgemm(const uint16_t* __restrict__ A,
           const uint16_t* __restrict__ B0, void* C0, int n0,
           const uint16_t* __restrict__ B1, void* C1, int n1,
           const uint16_t* __restrict__ B2, void* C2, int n2,
           const float* __restrict__ R, int K, int bfout) {
    constexpr int PW  = BK / 2 + 4;       // word pitch
    constexpr int CPR = BK / 8;           // 16B chunks per row
    constexpr int WM  = BM / 2;
    constexpr int WN  = BN / 4;
    constexpr int MT  = WM / 16;
    constexpr int NT  = WN / 8;
    constexpr int ACP = BM * CPR / 256;   // cp16 per thread per stage
    constexpr int BCP = BN * CPR / 256;

    extern __shared__ uint32_t smw[];
    uint32_t (*As)[BM][PW] = (uint32_t(*)[BM][PW])smw;
    uint32_t (*Bs)[BN][PW] = (uint32_t(*)[BN][PW])(smw + 2 * BM * PW);

    int tid  = threadIdx.x;
    int wid  = tid >> 5;
    int lane = tid & 31;
    int g    = lane >> 2;
    int cq   = lane & 3;
    int l15  = lane & 15;
    int h4   = (lane >> 4) * 4;
    int wm   = (wid & 1) * WM;
    int wn   = (wid >> 1) * WN;
    int r0   = blockIdx.y * BM;
    int c0   = blockIdx.x * BN;

    const uint16_t* Bseg;
    void* Cseg;
    int nseg, segc, segi;
    if (c0 < n0)           { Bseg = B0; Cseg = C0; nseg = n0; segc = c0; segi = 0; }
    else if (c0 < n0 + n1) { Bseg = B1; Cseg = C1; nseg = n1; segc = c0 - n0; segi = 1; }
    else                   { Bseg = B2; Cseg = C2; nseg = n2; segc = c0 - n0 - n1; segi = 2; }
    bool bfo = (bfout >> segi) & 1;

    float acc[MT][NT][4];
    #pragma unroll
    for (int t = 0; t < MT; t++)
        #pragma unroll
        for (int u = 0; u < NT; u++)
            #pragma unroll
            for (int i = 0; i < 4; i++) acc[t][u][i] = 0.0f;

    uint32_t aBase = s2u(&As[0][0][0]);
    uint32_t bBase = s2u(&Bs[0][0][0]);

    // stage 0
    #pragma unroll
    for (int t = 0; t < ACP; t++) {
        int idx = tid + t * 256;
        int ar = idx / CPR, ch = idx % CPR;
        cp16(s2u(&As[0][ar][ch * 4]), A + (size_t)(r0 + ar) * K + ch * 8);
    }
    #pragma unroll
    for (int t = 0; t < BCP; t++) {
        int idx = tid + t * 256;
        int br = idx / CPR, ch = idx % CPR;
        cp16(s2u(&Bs[0][br][ch * 4]), Bseg + (size_t)(segc + br) * K + ch * 8);
    }
    cp_commit();

    int NKB = K / BK;
    for (int kb = 0; kb < NKB; kb++) {
        int b = kb & 1;
        cp_wait<0>();
        __syncthreads();   // buffer kb ready; all warps done reading buf b^1

        if (kb + 1 < NKB) {
            int k0 = (kb + 1) * BK;
            #pragma unroll
            for (int t = 0; t < ACP; t++) {
                int idx = tid + t * 256;
                int ar = idx / CPR, ch = idx % CPR;
                cp16(s2u(&As[b ^ 1][ar][ch * 4]),
                     A + (size_t)(r0 + ar) * K + k0 + ch * 8);
            }
            #pragma unroll
            for (int t = 0; t < BCP; t++) {
                int idx = tid + t * 256;
                int br = idx / CPR, ch = idx % CPR;
                cp16(s2u(&Bs[b ^ 1][br][ch * 4]),
                     Bseg + (size_t)(segc + br) * K + k0 + ch * 8);
            }
            cp_commit();
        }

        uint32_t aB = aBase + (uint32_t)(b * BM * PW * 4);
        uint32_t bB = bBase + (uint32_t)(b * BN * PW * 4);

        #pragma unroll
        for (int k16 = 0; k16 < BK / 16; k16++) {
            int kw = k16 * 8 + h4;
            uint32_t af[MT][4];
            #pragma unroll
            for (int t = 0; t < MT; t++)
                ldsm_x4(af[t][0], af[t][1], af[t][2], af[t][3],
                        aB + (uint32_t)(((wm + 16 * t + l15) * PW + kw) * 4));
            uint32_t bf[NT][2];
            #pragma unroll
            for (int u2 = 0; u2 < NT / 2; u2++)
                ldsm_x4(bf[2 * u2][0], bf[2 * u2 + 1][0],
                        bf[2 * u2][1], bf[2 * u2 + 1][1],
                        bB + (uint32_t)(((wn + 16 * u2 + l15) * PW + kw) * 4));
            #pragma unroll
            for (int t = 0; t < MT; t++)
                #pragma unroll
                for (int u = 0; u < NT; u++)
                    mma_bf16(acc[t][u], af[t][0], af[t][1], af[t][2], af[t][3],
                             bf[u][0], bf[u][1]);
        }
    }

    #pragma unroll
    for (int t = 0; t < MT; t++) {
        int row = r0 + wm + 16 * t + g;
        #pragma unroll
        for (int u = 0; u < NT; u++) {
            int col = segc + wn + 8 * u + 2 * cq;
            size_t off0 = (size_t)row * nseg + col;
            size_t off1 = (size_t)(row + 8) * nseg + col;
            if (bfo) {
                uint16_t* Cb = (uint16_t*)Cseg;
                *(uint32_t*)(Cb + off0) = pack_bf16(acc[t][u][0], acc[t][u][1]);
                *(uint32_t*)(Cb + off1) = pack_bf16(acc[t][u][2], acc[t][u][3]);
            } else {
                float* Cf = (float*)Cseg;
                float2 r0v = make_float2(0.f, 0.f), r1v = make_float2(0.f, 0.f);
                if (R) {
                    r0v = *(const float2*)(R + off0);
                    r1v = *(const float2*)(R + off1);
                }
                *(float2*)(Cf + off0) = make_float2(acc[t][u][0] + r0v.x,
                                                    acc[t][u][1] + r0v.y);
                *(float2*)(Cf + off1) = make_float2(acc[t][u][2] + r1v.x,
                                                    acc[t][u][3] + r1v.y);
            }
        }
    }
}

// ---------------------------------------------------------------------------
// Fast RoPE + qk_norm on bf16 q/k: one block per s, 20 warps = 20 heads.
// Q scaled by 1/8 (exact pow2; folded softmax scale).
// ---------------------------------------------------------------------------
__global__ __launch_bounds__(640)
void rope_qknorm_fast(uint16_t* __restrict__ q, uint16_t* __restrict__ k,
                      float base) {
    __shared__ float scs[32], ssn[32];
    int s   = blockIdx.x;
    int tid = threadIdx.x;
    int w   = tid >> 5;
    int i   = tid & 31;

    if (tid < 32) {
        float invf = powf(base, -((float)(2 * tid) / (float)HDIM));
        float ang = (float)s * invf;
        sincosf(ang, &ssn[tid], &scs[tid]);
    }
    __syncthreads();

    uint32_t* p;
    float scale;
    if (w < NH) { p = (uint32_t*)(q + (size_t)s * DMODEL + w * HDIM); scale = 0.125f; }
    else        { p = (uint32_t*)(k + (size_t)s * LATD + (w - NH) * HDIM); scale = 1.0f; }

    uint32_t xw = p[i];
    float xe = bf_lo(xw), xo = bf_hi(xw);
    float cs = scs[i], sn = ssn[i];
    float re = xe * cs - xo * sn;
    float ro = xe * sn + xo * cs;

    float ss = re * re + ro * ro;
    #pragma unroll
    for (int o = 16; o > 0; o >>= 1)
        ss += __shfl_xor_sync(0xffffffffu, ss, o);

    float r = rsqrtf(ss / (float)HDIM + 1e-6f) * scale;
    p[i] = pack_bf16(re * r, ro * r);
}

// ---------------------------------------------------------------------------
// BF16 mma flash attention. Block = (64-q tile, head), 128 threads / 4 warps.
// Fixed-max softmax (scores in [-8,8] from qk_norm + folded 1/8 scale).
// Q staged transiently through Vs[1] (freed before first prefetch touches it)
// => SMEM = Ks[2][64]+Vs[2][64] only = 36864 B => 4 CTAs/SM.
// ---------------------------------------------------------------------------
#define APW 36
__global__ __launch_bounds__(128, 4)
void fattn_mma(const uint16_t* __restrict__ Q, const uint16_t* __restrict__ K,
               const uint16_t* __restrict__ V, uint16_t* __restrict__ O,
               int win) {
    extern __shared__ uint32_t smw[];
    uint32_t (*Ks)[64][APW] = (uint32_t(*)[64][APW])smw;
    uint32_t (*Vs)[64][APW] = (uint32_t(*)[64][APW])(smw + 2 * 64 * APW);

    int qt  = gridDim.x - 1 - blockIdx.x;   // heavy tiles first
    int h   = blockIdx.y;
    int kvh = h >> 2;
    int tid = threadIdx.x;
    int wid = tid >> 5;
    int lane = tid & 31;
    int g   = lane >> 2;
    int cq  = lane & 3;
    int l15 = lane & 15;
    int h4  = (lane >> 4) * 4;
    int m0  = wid * 16;
    int q0  = qt * 64;

    int jt0 = 0;
    if (win > 0) { jt0 = qt - 4; if (jt0 < 0) jt0 = 0; }

    // stage first K/V tile into buffer 0
    {
        int j0 = jt0 * 64;
        #pragma unroll
        for (int t = 0; t < 4; t++) {
            int idx = tid + t * 128;
            int jj = idx >> 3, ch = idx & 7;
            cp16(s2u(&Ks[0][jj][ch * 4]),
                 K + (size_t)(j0 + jj) * LATD + kvh * HDIM + ch * 8);
            cp16(s2u(&Vs[0][jj][ch * 4]),
                 V + (size_t)(j0 + jj) * LATD + kvh * HDIM + ch * 8);
        }
        cp_commit();
    }

    // stage Q transiently in Vs[1] (bf16, pre-scaled by 1/8)
    uint32_t* qstage = &Vs[1][0][0];
    #pragma unroll
    for (int t = 0; t < 4; t++) {
        int idx = tid + t * 128;
        int qi = idx >> 3, ch = idx & 7;
        *(uint4*)&qstage[qi * APW + ch * 4] =
            *(const uint4*)(Q + (size_t)(q0 + qi) * DMODEL + h * HDIM + ch * 8);
    }
    __syncthreads();

    // hoist Q fragments via ldmatrix (4 k16 windows over HDIM)
    uint32_t qBase = s2u(qstage);
    uint32_t qf[4][4];
    #pragma unroll
    for (int k16 = 0; k16 < 4; k16++)
        ldsm_x4(qf[k16][0], qf[k16][1], qf[k16][2], qf[k16][3],
                qBase + (uint32_t)(((m0 + l15) * APW + k16 * 8 + h4) * 4));

    float o[8][4];
    #pragma unroll
    for (int u = 0; u < 8; u++)
        #pragma unroll
        for (int i = 0; i < 4; i++) o[u][i] = 0.0f;
    float lrow0 = 0.0f, lrow1 = 0.0f;

    int row0 = q0 + m0 + g;
    int row1 = row0 + 8;
    uint32_t kBase = s2u(&Ks[0][0][0]);
    uint32_t vBase = s2u(&Vs[0][0][0]);

    for (int jt = jt0; jt <= qt; jt++) {
        int b = (jt - jt0) & 1;
        cp_wait<0>();
        __syncthreads();   // tile jt ready; Q fragments consumed by all warps

        if (jt < qt) {
            int j0 = (jt + 1) * 64;
            #pragma unroll
            for (int t = 0; t < 4; t++) {
                int idx = tid + t * 128;
                int jj = idx >> 3, ch = idx & 7;
                cp16(s2u(&Ks[b ^ 1][jj][ch * 4]),
                     K + (size_t)(j0 + jj) * LATD + kvh * HDIM + ch * 8);
                cp16(s2u(&Vs[b ^ 1][jj][ch * 4]),
                     V + (size_t)(j0 + jj) * LATD + kvh * HDIM + ch * 8);
            }
            cp_commit();
        }

        int j0 = jt * 64;
        uint32_t kB = kBase + (uint32_t)(b * 64 * APW * 4);
        uint32_t vB = vBase + (uint32_t)(b * 64 * APW * 4);

        // S = Q K^T
        float s[8][4];
        #pragma unroll
        for (int u = 0; u < 8; u++)
            #pragma unroll
            for (int i = 0; i < 4; i++) s[u][i] = 0.0f;

        #pragma unroll
        for (int k16 = 0; k16 < 4; k16++) {
            int kw = k16 * 8 + h4;
            #pragma unroll
            for (int u2 = 0; u2 < 4; u2++) {
                uint32_t b00, b01, b10, b11;
                ldsm_x4(b00, b10, b01, b11,
                        kB + (uint32_t)(((u2 * 16 + l15) * APW + kw) * 4));
                mma_bf16(s[2 * u2],     qf[k16][0], qf[k16][1], qf[k16][2],
                         qf[k16][3], b00, b01);
                mma_bf16(s[2 * u2 + 1], qf[k16][0], qf[k16][1], qf[k16][2],
                         qf[k16][3], b10, b11);
            }
        }

        // mask (skipped for interior fully-visible tiles)
        bool fullvis = (jt < qt) && (win == 0 || (q0 + 63 - j0) < win);
        if (!fullvis) {
            #pragma unroll
            for (int u = 0; u < 8; u++) {
                int col = j0 + u * 8 + 2 * cq;
                #pragma unroll
                for (int i = 0; i < 4; i++) {
                    int q  = (i < 2) ? row0 : row1;
                    int kj = col + (i & 1);
                    bool vis = (kj <= q) && (win == 0 || (q - kj) < win);
                    if (!vis) s[u][i] = -1e30f;
                }
            }
        }

        // softmax with FIXED max = 8 (scores bounded by qk_norm)
        float rs0 = 0.0f, rs1 = 0.0f;
        #pragma unroll
        for (int u = 0; u < 8; u++) {
            float p0 = __expf(s[u][0] - 8.0f);
            float p1 = __expf(s[u][1] - 8.0f);
            float p2 = __expf(s[u][2] - 8.0f);
            float p3 = __expf(s[u][3] - 8.0f);
            s[u][0] = p0; s[u][1] = p1; s[u][2] = p2; s[u][3] = p3;
            rs0 += p0 + p1;
            rs1 += p2 + p3;
        }
        #pragma unroll
        for (int off = 1; off <= 2; off <<= 1) {
            rs0 += __shfl_xor_sync(0xffffffffu, rs0, off);
            rs1 += __shfl_xor_sync(0xffffffffu, rs1, off);
        }
        lrow0 += rs0;
        lrow1 += rs1;

        // P fragments directly from S accumulators (no SMEM round-trip)
        uint32_t pf[4][4];
        #pragma unroll
        for (int w = 0; w < 4; w++) {
            pf[w][0] = pack_bf16(s[2 * w][0],     s[2 * w][1]);
            pf[w][1] = pack_bf16(s[2 * w][2],     s[2 * w][3]);
            pf[w][2] = pack_bf16(s[2 * w + 1][0], s[2 * w + 1][1]);
            pf[w][3] = pack_bf16(s[2 * w + 1][2], s[2 * w + 1][3]);
        }

        // O += P @ V  (V trans-ldmatrix from [key][hd])
        #pragma unroll
        for (int w = 0; w < 4; w++) {
            #pragma unroll
            for (int u2 = 0; u2 < 4; u2++) {
                uint32_t c00, c01, c10, c11;
                ldsm_x4_t(c00, c01, c10, c11,
                          vB + (uint32_t)(((w * 16 + l15) * APW + u2 * 8 + h4) * 4));
                mma_bf16(o[2 * u2],     pf[w][0], pf[w][1], pf[w][2], pf[w][3],
                         c00, c01);
                mma_bf16(o[2 * u2 + 1], pf[w][0], pf[w][1], pf[w][2], pf[w][3],
                         c10, c11);
            }
        }
    }

    float inv0 = 1.0f / lrow0;
    float inv1 = 1.0f / lrow1;
    #pragma unroll
    for (int u = 0; u < 8; u++) {
        int col = u * 8 + 2 * cq;
        *(uint32_t*)(O + (size_t)row0 * DMODEL + h * HDIM + col) =
            pack_bf16(o[u][0] * inv0, o[u][1] * inv0);
        *(uint32_t*)(O + (size_t)row1 * DMODEL + h * HDIM + col) =
            pack_bf16(o[u][2] * inv1, o[u][3] * inv1);
    }
}

// ---------------------------------------------------------------------------
// Launch
// ---------------------------------------------------------------------------
extern "C" void kernel_launch(void* const* d_in, const int* in_sizes, int n_in,
                              void* d_out, int out_size) {
    (void)in_sizes; (void)n_in; (void)out_size;

    const float* hidden   = (const float*)d_in[0];
    const float* norm1_w  = (const float*)d_in[1];
    const float* norm2_w  = (const float*)d_in[2];
    const float* w_g_wq   = (const float*)d_in[3];
    const float* w_g_kvdn = (const float*)d_in[4];
    const float* w_g_k_up = (const float*)d_in[5];
    const float* w_g_v_up = (const float*)d_in[6];
    const float* w_g_wo   = (const float*)d_in[7];
    const float* w_l_wq   = (const float*)d_in[8];
    const float* w_l_wk   = (const float*)d_in[9];
    const float* w_l_wv   = (const float*)d_in[10];
    const float* w_l_wo   = (const float*)d_in[11];
    float* out = (float*)d_out;

    uint16_t *x1, *q, *lat, *k, *v, *attn, *gw;
    cudaGetSymbolAddress((void**)&x1,   g_x1);
    cudaGetSymbolAddress((void**)&q,    g_q);
    cudaGetSymbolAddress((void**)&lat,  g_lat);
    cudaGetSymbolAddress((void**)&k,    g_k);
    cudaGetSymbolAddress((void**)&v,    g_v);
    cudaGetSymbolAddress((void**)&attn, g_attn);
    cudaGetSymbolAddress((void**)&gw,   g_w);

    const int GEMM128_SMEM = 2 * (128 * 36 + 128 * 36) * 4;  // 73728 (BK=64)
    const int GEMM64_SMEM  = 2 * (64 * 36 + 64 * 36) * 4;    // 36864 (BK=64)
    const int ATTN_SMEM    = 4 * 64 * APW * 4;               // 36864

    cudaFuncSetAttribute(bgemm<128, 128, 64>,
                         cudaFuncAttributeMaxDynamicSharedMemorySize, GEMM128_SMEM);
    cudaFuncSetAttribute(bgemm<64, 64, 64>,
                         cudaFuncAttributeMaxDynamicSharedMemorySize, GEMM64_SMEM);
    cudaFuncSetAttribute(fattn_mma,
                         cudaFuncAttributeMaxDynamicSharedMemorySize, ATTN_SMEM);

    dim3 gridAttn(SEQ / 64, NH);   // (32, 16)

    // ---- Fused prep: weight transpose+convert ++ layer-1 rmsnorm ----
    prep_kernel<<<7040, 256>>>(gw,
        w_g_wq, w_g_kvdn, w_g_k_up, w_g_v_up, w_g_wo,
        w_l_wq, w_l_wk, w_l_wv, w_l_wo,
        hidden, norm1_w, x1);

    // ---- Layer 1: global latent attention ----
    bgemm<128, 128, 64><<<dim3(10, 16), 256, GEMM128_SMEM>>>(
        x1, gw + GWQ, q, DMODEL, gw + GKV, lat, LATD,
        nullptr, nullptr, 0, nullptr, DMODEL, /*bfout=*/3);
    bgemm<64, 64, 64><<<dim3(8, 32), 256, GEMM64_SMEM>>>(
        lat, gw + GKUP, k, LATD, gw + GVUP, v, LATD,
        nullptr, nullptr, 0, nullptr, LATD, /*bfout=*/3);
    rope_qknorm_fast<<<SEQ, 640>>>(q, k, 1000000.0f);
    fattn_mma<<<gridAttn, 128, ATTN_SMEM>>>(q, k, v, attn, /*win=*/0);
    bgemm<128, 128, 64><<<dim3(8, 16), 256, GEMM128_SMEM>>>(
        attn, gw + GWO, out, DMODEL, nullptr, nullptr, 0,
        nullptr, nullptr, 0, hidden, DMODEL, /*bfout=*/0);

    // ---- Layer 2: local GQA attention ----
    rmsnorm_kernel<<<SEQ, 256>>>(out, norm2_w, x1);
    bgemm<128, 128, 64><<<dim3(12, 16), 256, GEMM128_SMEM>>>(
        x1, gw + LWQ, q, DMODEL, gw + LWK, k, LATD,
        gw + LWV, v, LATD, nullptr, DMODEL, /*bfout=*/7);
    rope_qknorm_fast<<<SEQ, 640>>>(q, k, 10000.0f);
    fattn_mma<<<gridAttn, 128, ATTN_SMEM>>>(q, k, v, attn, /*win=*/WINSZ);
    bgemm<128, 128, 64><<<dim3(8, 16), 256, GEMM128_SMEM>>>(
        attn, gw + LWO, out, DMODEL, nullptr, nullptr, 0,
        nullptr, nullptr, 0, out, DMODEL, /*bfout=*/0);
}